// round 2
// baseline (speedup 1.0000x reference)
#include <cuda_runtime.h>
#include <cuda_bf16.h>
#include <math.h>

// Problem constants
#define Tn   1024
#define Dn   1024
#define Hn   16
#define HDn  64
#define An   1024          // H*HD
#define Fn   4096
#define Bn   2
#define BTn  (Bn*Tn)       // 2048

// ---------------- scratch (allocation-free) ----------------
__device__ float g_qkv_u[(size_t)Bn*Tn*3*An];     // 6.29M
__device__ float g_qkv_v[(size_t)Bn*Tn*3*An];
__device__ float g_sim1[(size_t)Bn*Hn*Tn*Tn];     // 33.55M
__device__ float g_sim2[(size_t)Bn*Hn*Tn*Tn];
__device__ float g_comb[(size_t)Bn*Hn*Tn*Tn];
__device__ float g_head[(size_t)Bn*Tn*An];        // 2.10M
__device__ float g_proj[(size_t)Bn*Tn*Dn];
__device__ float g_o1  [(size_t)Bn*Tn*Dn];
__device__ float g_ffh [(size_t)Bn*Tn*Fn];        // 8.39M

// =====================================================================
// 128x128 tile SGEMM, 8x8 per thread, BK=8, 256 threads.
// C[m,n] = alpha * sum_k A[m,k]*B[k,n]   (TRANSB: B[n,k])
// then +bias[n], relu, mask-fill(1e-32).
// Batched over blockIdx.z: off = (z/Hdiv)*s1 + (z%Hdiv)*s2.
// Requires M%128==0, N%128==0, K%8==0.
// =====================================================================
template<bool TRANSB>
__global__ __launch_bounds__(256)
void gemm128_k(const float* __restrict__ A, const float* __restrict__ B,
               const float* __restrict__ bias, const int* __restrict__ mask,
               float* __restrict__ C,
               int K, int lda, int ldb, int ldc,
               long long sA1, long long sA2, long long sB1, long long sB2,
               long long sC1, long long sC2,
               int Hdiv, int maskStride, float alpha, int relu)
{
    int z  = blockIdx.z;
    int zb = z / Hdiv, zh = z % Hdiv;
    A += zb * sA1 + zh * sA2;
    B += zb * sB1 + zh * sB2;
    C += zb * sC1 + zh * sC2;
    if (mask) mask += (long long)zb * maskStride;

    __shared__ float As[8][132];
    __shared__ float Bs[8][132];

    int tid = threadIdx.x;
    int m0 = blockIdx.y * 128, n0 = blockIdx.x * 128;

    int ar = tid >> 1;             // 0..127
    int ac = (tid & 1) << 2;       // 0,4
    int br = tid >> 5;             // 0..7   (NN path)
    int bc = (tid & 31) << 2;      // 0..124

    int tx = tid & 15, ty = tid >> 4;

    float acc[8][8] = {};

    for (int k0 = 0; k0 < K; k0 += 8) {
        float4 av = *reinterpret_cast<const float4*>(&A[(size_t)(m0 + ar) * lda + k0 + ac]);
        As[ac + 0][ar] = av.x; As[ac + 1][ar] = av.y;
        As[ac + 2][ar] = av.z; As[ac + 3][ar] = av.w;
        if (TRANSB) {
            float4 bv = *reinterpret_cast<const float4*>(&B[(size_t)(n0 + ar) * ldb + k0 + ac]);
            Bs[ac + 0][ar] = bv.x; Bs[ac + 1][ar] = bv.y;
            Bs[ac + 2][ar] = bv.z; Bs[ac + 3][ar] = bv.w;
        } else {
            float4 bv = *reinterpret_cast<const float4*>(&B[(size_t)(k0 + br) * ldb + n0 + bc]);
            *reinterpret_cast<float4*>(&Bs[br][bc]) = bv;
        }
        __syncthreads();
#pragma unroll
        for (int kk = 0; kk < 8; kk++) {
            float a0[4], a1[4], b0[4], b1[4];
            *reinterpret_cast<float4*>(a0) = *reinterpret_cast<const float4*>(&As[kk][ty << 2]);
            *reinterpret_cast<float4*>(a1) = *reinterpret_cast<const float4*>(&As[kk][(ty << 2) + 64]);
            *reinterpret_cast<float4*>(b0) = *reinterpret_cast<const float4*>(&Bs[kk][tx << 2]);
            *reinterpret_cast<float4*>(b1) = *reinterpret_cast<const float4*>(&Bs[kk][(tx << 2) + 64]);
#pragma unroll
            for (int i = 0; i < 4; i++)
#pragma unroll
                for (int j = 0; j < 4; j++) {
                    acc[i][j]         += a0[i] * b0[j];
                    acc[i][j + 4]     += a0[i] * b1[j];
                    acc[i + 4][j]     += a1[i] * b0[j];
                    acc[i + 4][j + 4] += a1[i] * b1[j];
                }
        }
        __syncthreads();
    }

#pragma unroll
    for (int ii = 0; ii < 8; ii++) {
        int mi = m0 + (ty << 2) + ((ii < 4) ? ii : (60 + ii));
        size_t rowoff = (size_t)mi * ldc;
#pragma unroll
        for (int jj = 0; jj < 8; jj++) {
            int col = n0 + (tx << 2) + ((jj < 4) ? jj : (60 + jj));
            float v = acc[ii][jj] * alpha;
            if (bias) v += bias[col];
            if (relu) v = fmaxf(v, 0.f);
            if (mask && mask[col] == 0) v = 1e-32f;
            C[rowoff + col] = v;
        }
    }
}

// =====================================================================
// 64x64 tile SGEMM (for N=64 att@V), 4x4 per thread, BK=16.
// =====================================================================
#define TILE 64
#define BKs  16

template<bool TRANSB>
__global__ __launch_bounds__(256)
void gemm_k(const float* __restrict__ A, const float* __restrict__ B,
            const float* __restrict__ bias, const int* __restrict__ mask,
            float* __restrict__ C,
            int K, int lda, int ldb, int ldc,
            long long sA1, long long sA2, long long sB1, long long sB2,
            long long sC1, long long sC2,
            int Hdiv, int maskStride, float alpha, int relu)
{
    int z  = blockIdx.z;
    int zb = z / Hdiv, zh = z % Hdiv;
    A += zb * sA1 + zh * sA2;
    B += zb * sB1 + zh * sB2;
    C += zb * sC1 + zh * sC2;
    if (mask) mask += (long long)zb * maskStride;

    __shared__ float As[BKs][TILE + 4];
    __shared__ float Bs[BKs][TILE + 4];

    int tid = threadIdx.x;
    int tx = tid & 15, ty = tid >> 4;
    int m0 = blockIdx.y * TILE, n0 = blockIdx.x * TILE;
    int lr = tid >> 2;           // 0..63
    int lc = (tid & 3) << 2;     // 0,4,8,12

    float acc[4][4] = {};

    for (int k0 = 0; k0 < K; k0 += BKs) {
        float4 av = *reinterpret_cast<const float4*>(&A[(size_t)(m0 + lr) * lda + k0 + lc]);
        As[lc + 0][lr] = av.x; As[lc + 1][lr] = av.y;
        As[lc + 2][lr] = av.z; As[lc + 3][lr] = av.w;
        if (TRANSB) {
            float4 bv = *reinterpret_cast<const float4*>(&B[(size_t)(n0 + lr) * ldb + k0 + lc]);
            Bs[lc + 0][lr] = bv.x; Bs[lc + 1][lr] = bv.y;
            Bs[lc + 2][lr] = bv.z; Bs[lc + 3][lr] = bv.w;
        } else {
            int brw = tid >> 4;            // 0..15
            int bcl = (tid & 15) << 2;     // 0..60
            float4 bv = *reinterpret_cast<const float4*>(&B[(size_t)(k0 + brw) * ldb + n0 + bcl]);
            *reinterpret_cast<float4*>(&Bs[brw][bcl]) = bv;
        }
        __syncthreads();
#pragma unroll
        for (int kk = 0; kk < BKs; kk++) {
            float4 a4 = *reinterpret_cast<const float4*>(&As[kk][ty << 2]);
            float4 b4 = *reinterpret_cast<const float4*>(&Bs[kk][tx << 2]);
            float ar[4] = {a4.x, a4.y, a4.z, a4.w};
            float br[4] = {b4.x, b4.y, b4.z, b4.w};
#pragma unroll
            for (int i = 0; i < 4; i++)
#pragma unroll
                for (int j = 0; j < 4; j++) acc[i][j] += ar[i] * br[j];
        }
        __syncthreads();
    }

#pragma unroll
    for (int i = 0; i < 4; i++) {
        size_t rowoff = (size_t)(m0 + (ty << 2) + i) * ldc;
#pragma unroll
        for (int j = 0; j < 4; j++) {
            int col = n0 + (tx << 2) + j;
            float v = acc[i][j] * alpha;
            if (bias) v += bias[col];
            if (relu) v = fmaxf(v, 0.f);
            if (mask && mask[col] == 0) v = 1e-32f;
            C[rowoff + col] = v;
        }
    }
}

// ---------------- row softmax over 1024 cols, in place ----------------
__global__ __launch_bounds__(256)
void softmax_k(float* __restrict__ P)
{
    __shared__ float sdata[8];
    size_t row = blockIdx.x;
    float4* p = reinterpret_cast<float4*>(P + row * (size_t)Tn);
    int tid = threadIdx.x;
    float4 v = p[tid];
    float m = fmaxf(fmaxf(v.x, v.y), fmaxf(v.z, v.w));
#pragma unroll
    for (int o = 16; o; o >>= 1) m = fmaxf(m, __shfl_xor_sync(0xffffffffu, m, o));
    if ((tid & 31) == 0) sdata[tid >> 5] = m;
    __syncthreads();
    if (tid == 0) {
        float t = sdata[0];
#pragma unroll
        for (int i = 1; i < 8; i++) t = fmaxf(t, sdata[i]);
        sdata[0] = t;
    }
    __syncthreads();
    m = sdata[0];
    v.x = expf(v.x - m); v.y = expf(v.y - m);
    v.z = expf(v.z - m); v.w = expf(v.w - m);
    float s = v.x + v.y + v.z + v.w;
#pragma unroll
    for (int o = 16; o; o >>= 1) s += __shfl_xor_sync(0xffffffffu, s, o);
    __syncthreads();
    if ((tid & 31) == 0) sdata[tid >> 5] = s;
    __syncthreads();
    if (tid == 0) {
        float t = 0.f;
#pragma unroll
        for (int i = 0; i < 8; i++) t += sdata[i];
        sdata[0] = t;
    }
    __syncthreads();
    float inv = 1.f / sdata[0];
    v.x *= inv; v.y *= inv; v.z *= inv; v.w *= inv;
    p[tid] = v;
}

// ---------------- out = LayerNorm(X + Y) * g + b (row of 1024) ----------------
__global__ __launch_bounds__(256)
void add_ln_k(const float* __restrict__ X, const float* __restrict__ Y,
              const float* __restrict__ g, const float* __restrict__ b,
              float* __restrict__ out)
{
    __shared__ float s1[8], s2[8];
    size_t row = (size_t)blockIdx.x * Dn;
    int tid = threadIdx.x;
    float4 x = *reinterpret_cast<const float4*>(X + row + tid * 4);
    float4 y = *reinterpret_cast<const float4*>(Y + row + tid * 4);
    float4 v; v.x = x.x + y.x; v.y = x.y + y.y; v.z = x.z + y.z; v.w = x.w + y.w;
    float sum = v.x + v.y + v.z + v.w;
    float sq  = v.x*v.x + v.y*v.y + v.z*v.z + v.w*v.w;
#pragma unroll
    for (int o = 16; o; o >>= 1) {
        sum += __shfl_xor_sync(0xffffffffu, sum, o);
        sq  += __shfl_xor_sync(0xffffffffu, sq,  o);
    }
    if ((tid & 31) == 0) { s1[tid >> 5] = sum; s2[tid >> 5] = sq; }
    __syncthreads();
    if (tid == 0) {
        float a = 0.f, c = 0.f;
#pragma unroll
        for (int i = 0; i < 8; i++) { a += s1[i]; c += s2[i]; }
        s1[0] = a; s2[0] = c;
    }
    __syncthreads();
    float mean = s1[0] * (1.f / Dn);
    float var  = s2[0] * (1.f / Dn) - mean * mean;
    float inv  = rsqrtf(var + 1e-5f);
    float4 gg = *reinterpret_cast<const float4*>(g + tid * 4);
    float4 bb = *reinterpret_cast<const float4*>(b + tid * 4);
    float4 o;
    o.x = (v.x - mean) * inv * gg.x + bb.x;
    o.y = (v.y - mean) * inv * gg.y + bb.y;
    o.z = (v.z - mean) * inv * gg.z + bb.z;
    o.w = (v.w - mean) * inv * gg.w + bb.w;
    *reinterpret_cast<float4*>(out + row + tid * 4) = o;
}

// ---------------- host side ----------------
static void launch_gemm128(bool transb,
                           const float* A, const float* B, const float* bias, const int* mask,
                           float* C, int M, int N, int K, int lda, int ldb, int ldc,
                           long long sA1, long long sA2, long long sB1, long long sB2,
                           long long sC1, long long sC2,
                           int Hdiv, int maskStride, float alpha, int relu, int batches)
{
    dim3 grid(N / 128, M / 128, batches), block(256);
    if (transb)
        gemm128_k<true><<<grid, block>>>(A, B, bias, mask, C, K, lda, ldb, ldc,
                                         sA1, sA2, sB1, sB2, sC1, sC2, Hdiv, maskStride, alpha, relu);
    else
        gemm128_k<false><<<grid, block>>>(A, B, bias, mask, C, K, lda, ldb, ldc,
                                          sA1, sA2, sB1, sB2, sC1, sC2, Hdiv, maskStride, alpha, relu);
}

static void launch_gemm64(bool transb,
                          const float* A, const float* B, const float* bias, const int* mask,
                          float* C, int M, int N, int K, int lda, int ldb, int ldc,
                          long long sA1, long long sA2, long long sB1, long long sB2,
                          long long sC1, long long sC2,
                          int Hdiv, int maskStride, float alpha, int relu, int batches)
{
    dim3 grid(N / TILE, M / TILE, batches), block(256);
    if (transb)
        gemm_k<true><<<grid, block>>>(A, B, bias, mask, C, K, lda, ldb, ldc,
                                      sA1, sA2, sB1, sB2, sC1, sC2, Hdiv, maskStride, alpha, relu);
    else
        gemm_k<false><<<grid, block>>>(A, B, bias, mask, C, K, lda, ldb, ldc,
                                       sA1, sA2, sB1, sB2, sC1, sC2, Hdiv, maskStride, alpha, relu);
}

extern "C" void kernel_launch(void* const* d_in, const int* in_sizes, int n_in,
                              void* d_out, int out_size)
{
    const float* src = (const float*)d_in[0];
    const float* aux = (const float*)d_in[1];
    const float* Wu  = (const float*)d_in[2];
    const float* bu  = (const float*)d_in[3];
    const float* Wv  = (const float*)d_in[4];
    const float* bv  = (const float*)d_in[5];
    const float* Wo  = (const float*)d_in[6];
    const float* bo  = (const float*)d_in[7];
    const float* W1  = (const float*)d_in[8];
    const float* b1  = (const float*)d_in[9];
    const float* W2  = (const float*)d_in[10];
    const float* b2  = (const float*)d_in[11];
    const float* g1  = (const float*)d_in[12];
    const float* be1 = (const float*)d_in[13];
    const float* g2  = (const float*)d_in[14];
    const float* be2 = (const float*)d_in[15];
    const int* src_mask = (const int*)d_in[16];
    const int* aux_mask = (const int*)d_in[17];
    float* out = (float*)d_out;

    float *qkv_u, *qkv_v, *sim1, *sim2, *comb, *head, *proj, *o1, *ffh;
    cudaGetSymbolAddress((void**)&qkv_u, g_qkv_u);
    cudaGetSymbolAddress((void**)&qkv_v, g_qkv_v);
    cudaGetSymbolAddress((void**)&sim1,  g_sim1);
    cudaGetSymbolAddress((void**)&sim2,  g_sim2);
    cudaGetSymbolAddress((void**)&comb,  g_comb);
    cudaGetSymbolAddress((void**)&head,  g_head);
    cudaGetSymbolAddress((void**)&proj,  g_proj);
    cudaGetSymbolAddress((void**)&o1,    g_o1);
    cudaGetSymbolAddress((void**)&ffh,   g_ffh);

    const long long sQKV = (long long)Tn * 3 * An;   // per-batch stride in qkv
    const long long sHT2 = (long long)Hn * Tn * Tn;  // per-batch stride in sim/comb
    const long long sT2  = (long long)Tn * Tn;
    const long long sTA  = (long long)Tn * An;

    // ---- QKV projections (both streams)
    launch_gemm128(false, src, Wu, bu, nullptr, qkv_u, BTn, 3 * An, Dn, Dn, 3 * An, 3 * An,
                   0, 0, 0, 0, 0, 0, 1, 0, 1.f, 0, 1);
    launch_gemm128(false, aux, Wv, bv, nullptr, qkv_v, BTn, 3 * An, Dn, Dn, 3 * An, 3 * An,
                   0, 0, 0, 0, 0, 0, 1, 0, 1.f, 0, 1);

    // ---- sim1 = (Qu/8) @ Kv^T, mask cols by aux_mask; sim2 = (Qv/8) @ Ku^T, mask by src_mask
    launch_gemm128(true, qkv_u, qkv_v + An, nullptr, aux_mask, sim1,
                   Tn, Tn, HDn, 3 * An, 3 * An, Tn,
                   sQKV, HDn, sQKV, HDn, sHT2, sT2, Hn, Tn, 0.125f, 0, Bn * Hn);
    launch_gemm128(true, qkv_v, qkv_u + An, nullptr, src_mask, sim2,
                   Tn, Tn, HDn, 3 * An, 3 * An, Tn,
                   sQKV, HDn, sQKV, HDn, sHT2, sT2, Hn, Tn, 0.125f, 0, Bn * Hn);

    // ================= stream U =================
    // comb = sim1 @ sim2
    launch_gemm128(false, sim1, sim2, nullptr, nullptr, comb, Tn, Tn, Tn, Tn, Tn, Tn,
                   sHT2, sT2, sHT2, sT2, sHT2, sT2, Hn, 0, 1.f, 0, Bn * Hn);
    softmax_k<<<Bn * Hn * Tn, 256>>>(comb);
    // head = att @ Vu  (merged heads layout, N=64 -> 64-tile kernel)
    launch_gemm64(false, comb, qkv_u + 2 * An, nullptr, nullptr, head,
                  Tn, HDn, Tn, Tn, 3 * An, An,
                  sHT2, sT2, sQKV, HDn, sTA, HDn, Hn, 0, 1.f, 0, Bn * Hn);
    // proj = head @ Wo + bo
    launch_gemm128(false, head, Wo, bo, nullptr, proj, BTn, Dn, An, An, Dn, Dn,
                   0, 0, 0, 0, 0, 0, 1, 0, 1.f, 0, 1);
    add_ln_k<<<BTn, 256>>>(src, proj, g1, be1, o1);
    launch_gemm128(false, o1, W1, b1, nullptr, ffh, BTn, Fn, Dn, Dn, Fn, Fn,
                   0, 0, 0, 0, 0, 0, 1, 0, 1.f, 1, 1);
    launch_gemm128(false, ffh, W2, b2, nullptr, proj, BTn, Dn, Fn, Fn, Dn, Dn,
                   0, 0, 0, 0, 0, 0, 1, 0, 1.f, 0, 1);
    add_ln_k<<<BTn, 256>>>(o1, proj, g2, be2, out);

    // ================= stream V =================
    // comb = sim2 @ sim1
    launch_gemm128(false, sim2, sim1, nullptr, nullptr, comb, Tn, Tn, Tn, Tn, Tn, Tn,
                   sHT2, sT2, sHT2, sT2, sHT2, sT2, Hn, 0, 1.f, 0, Bn * Hn);
    softmax_k<<<Bn * Hn * Tn, 256>>>(comb);
    launch_gemm64(false, comb, qkv_v + 2 * An, nullptr, nullptr, head,
                  Tn, HDn, Tn, Tn, 3 * An, An,
                  sHT2, sT2, sQKV, HDn, sTA, HDn, Hn, 0, 1.f, 0, Bn * Hn);
    launch_gemm128(false, head, Wo, bo, nullptr, proj, BTn, Dn, An, An, Dn, Dn,
                   0, 0, 0, 0, 0, 0, 1, 0, 1.f, 0, 1);
    add_ln_k<<<BTn, 256>>>(aux, proj, g1, be1, o1);
    launch_gemm128(false, o1, W1, b1, nullptr, ffh, BTn, Fn, Dn, Dn, Fn, Fn,
                   0, 0, 0, 0, 0, 0, 1, 0, 1.f, 1, 1);
    launch_gemm128(false, ffh, W2, b2, nullptr, proj, BTn, Dn, Fn, Fn, Dn, Dn,
                   0, 0, 0, 0, 0, 0, 1, 0, 1.f, 0, 1);
    add_ln_k<<<BTn, 256>>>(o1, proj, g2, be2, out + (size_t)BTn * Dn);
}

// round 4
// speedup vs baseline: 1.3499x; 1.3499x over previous
#include <cuda_runtime.h>
#include <cuda_bf16.h>
#include <math.h>
#include <stdint.h>

// Problem constants
#define Tn   1024
#define Dn   1024
#define Hn   16
#define HDn  64
#define An   1024          // H*HD
#define Fn   4096
#define Bn   2
#define BTn  (Bn*Tn)       // 2048
#define ZHn  (Bn*Hn)       // 32

// ---------------- scratch (allocation-free) ----------------
__device__ float g_qkv_u[(size_t)Bn*Tn*3*An];
__device__ float g_qkv_v[(size_t)Bn*Tn*3*An];
__device__ float g_sim1[(size_t)ZHn*Tn*Tn];
__device__ float g_sim2[(size_t)ZHn*Tn*Tn];
__device__ float g_comb[(size_t)ZHn*Tn*Tn];
__device__ float g_head[(size_t)Bn*Tn*An];
__device__ float g_proj[(size_t)Bn*Tn*Dn];
__device__ float g_o1  [(size_t)Bn*Tn*Dn];
__device__ float g_ffh [(size_t)Bn*Tn*Fn];

// bf16 hi/lo splits of sim1/sim2 (row-major "A" layout and transposed "B" layout)
#define SIMELEMS ((size_t)ZHn*Tn*Tn)
__device__ __nv_bfloat16 g_s1h[SIMELEMS], g_s1l[SIMELEMS];
__device__ __nv_bfloat16 g_s2h[SIMELEMS], g_s2l[SIMELEMS];
__device__ __nv_bfloat16 g_s1th[SIMELEMS], g_s1tl[SIMELEMS];
__device__ __nv_bfloat16 g_s2th[SIMELEMS], g_s2tl[SIMELEMS];

// ===================== portable PTX helpers (sm_80+) =====================
__device__ __forceinline__ uint32_t smem_u32(const void* p) {
    uint32_t a;
    asm("{ .reg .u64 t; cvta.to.shared.u64 t, %1; cvt.u32.u64 %0, t; }" : "=r"(a) : "l"(p));
    return a;
}
#define SW128(off) ((off) ^ (((off) >> 3) & 0x70))

__device__ __forceinline__ void cp_async16(uint32_t saddr, const void* gptr) {
    asm volatile("cp.async.cg.shared.global [%0], [%1], 16;" :: "r"(saddr), "l"(gptr) : "memory");
}
__device__ __forceinline__ void cp_commit() {
    asm volatile("cp.async.commit_group;" ::: "memory");
}
template<int N>
__device__ __forceinline__ void cp_wait() {
    asm volatile("cp.async.wait_group %0;" :: "n"(N) : "memory");
}
__device__ __forceinline__ void ldsm4(uint32_t* r, uint32_t addr) {
    asm volatile("ldmatrix.sync.aligned.m8n8.x4.shared.b16 {%0,%1,%2,%3}, [%4];"
                 : "=r"(r[0]), "=r"(r[1]), "=r"(r[2]), "=r"(r[3]) : "r"(addr));
}
__device__ __forceinline__ void mma_bf16(float* c, const uint32_t* a, const uint32_t* b) {
    asm volatile("mma.sync.aligned.m16n8k16.row.col.f32.bf16.bf16.f32 "
                 "{%0,%1,%2,%3}, {%4,%5,%6,%7}, {%8,%9}, {%0,%1,%2,%3};"
                 : "+f"(c[0]), "+f"(c[1]), "+f"(c[2]), "+f"(c[3])
                 : "r"(a[0]), "r"(a[1]), "r"(a[2]), "r"(a[3]), "r"(b[0]), "r"(b[1]));
}

// ===================== bf16x3 comb MMA kernel (HMMA mma.sync) =====================
// C[z, m0:+128, n0:+128] = Ah@Bh^T + Ah@Bl^T + Al@Bh^T  (fp32 accum)
// A arrays: [z][m][k] bf16. B arrays: [z][n][k] bf16 (pre-transposed).
#define KC 64                        // k elems per chunk
#define MAT_BYTES 16384              // 128 rows * 128 B
#define STAGE_BYTES (4*MAT_BYTES)    // Ah, Al, Bh, Bl
#define NCHUNK (Tn/KC)               // 16
#define SMEM_DYN (2*STAGE_BYTES + 1024)

__global__ __launch_bounds__(256, 1)
void comb_mma_k(const __nv_bfloat16* __restrict__ Ah, const __nv_bfloat16* __restrict__ Al,
                const __nv_bfloat16* __restrict__ Bh, const __nv_bfloat16* __restrict__ Bl,
                float* __restrict__ C)
{
    extern __shared__ char smraw[];
    uint32_t raw  = smem_u32(smraw);
    uint32_t base = (raw + 1023u) & ~1023u;

    int tid = threadIdx.x, wid = tid >> 5, lane = tid & 31;
    int z = blockIdx.z, m0 = blockIdx.y * 128, n0 = blockIdx.x * 128;
    size_t zoff = (size_t)z * Tn * Tn;
    const __nv_bfloat16* pAh = Ah + zoff + (size_t)m0 * Tn;
    const __nv_bfloat16* pAl = Al + zoff + (size_t)m0 * Tn;
    const __nv_bfloat16* pBh = Bh + zoff + (size_t)n0 * Tn;
    const __nv_bfloat16* pBl = Bl + zoff + (size_t)n0 * Tn;
    float* pC = C + zoff + (size_t)m0 * Tn + n0;

    // per-thread load assignment: 4 16B chunks per matrix per stage
    int lr[4], lsw[4];
#pragma unroll
    for (int i = 0; i < 4; i++) {
        int q = tid + i * 256;        // 0..1023
        lr[i]  = q >> 3;              // row 0..127
        int c  = q & 7;               // 16B chunk in row
        lsw[i] = SW128(lr[i] * 128 + c * 16);
    }

    auto load_stage = [&](int s, int kc) {
        uint32_t sb = base + (uint32_t)s * STAGE_BYTES;
#pragma unroll
        for (int i = 0; i < 4; i++) {
            size_t go = (size_t)lr[i] * Tn + kc * KC + ((tid + i * 256) & 7) * 8;
            cp_async16(sb + 0 * MAT_BYTES + lsw[i], pAh + go);
            cp_async16(sb + 1 * MAT_BYTES + lsw[i], pAl + go);
            cp_async16(sb + 2 * MAT_BYTES + lsw[i], pBh + go);
            cp_async16(sb + 3 * MAT_BYTES + lsw[i], pBl + go);
        }
        cp_commit();
    };

    // warp layout: 4 (M) x 2 (N); warp tile 32x64
    int wm = (wid >> 1) * 32;
    int wn = (wid & 1) * 64;

    float acc[2][8][4];
#pragma unroll
    for (int a = 0; a < 2; a++)
#pragma unroll
        for (int b = 0; b < 8; b++)
#pragma unroll
            for (int c = 0; c < 4; c++) acc[a][b][c] = 0.f;

    // ldmatrix logical offsets (stage-relative), computed once
    // A (16x16 frag): lane -> row = (lane&15), colblock = lane>>4
    int a_row = wm + (lane & 15);
    int a_cb  = (lane >> 4) * 16;            // bytes
    // B (two 16x8 frags per x4): lane -> row = (l&7) + ((l>>4)<<3), colblock = (l>>3)&1
    int b_row = wn + (lane & 7) + ((lane >> 4) << 3);
    int b_cb  = ((lane >> 3) & 1) * 16;

    load_stage(0, 0);

    for (int c = 0; c < NCHUNK; c++) {
        if (c + 1 < NCHUNK) { load_stage((c + 1) & 1, c + 1); cp_wait<1>(); }
        else                { cp_wait<0>(); }
        __syncthreads();

        uint32_t sb = base + (uint32_t)(c & 1) * STAGE_BYTES;
        uint32_t sAh = sb, sAl = sb + MAT_BYTES, sBh = sb + 2 * MAT_BYTES, sBl = sb + 3 * MAT_BYTES;

#pragma unroll
        for (int ks = 0; ks < 4; ks++) {
            uint32_t ah[2][4], al[2][4];
            int acol = ks * 32 + a_cb;
#pragma unroll
            for (int mi = 0; mi < 2; mi++) {
                int sw = SW128((a_row + mi * 16) * 128 + acol);
                ldsm4(ah[mi], sAh + sw);
                ldsm4(al[mi], sAl + sw);
            }
            int bcol = ks * 32 + b_cb;
#pragma unroll
            for (int np = 0; np < 4; np++) {
                int sw = SW128((b_row + np * 16) * 128 + bcol);
                uint32_t bh[4], bl[4];
                ldsm4(bh, sBh + sw);
#pragma unroll
                for (int mi = 0; mi < 2; mi++) {
                    mma_bf16(acc[mi][np * 2 + 0], ah[mi], bh + 0);
                    mma_bf16(acc[mi][np * 2 + 1], ah[mi], bh + 2);
                    mma_bf16(acc[mi][np * 2 + 0], al[mi], bh + 0);
                    mma_bf16(acc[mi][np * 2 + 1], al[mi], bh + 2);
                }
                ldsm4(bl, sBl + sw);
#pragma unroll
                for (int mi = 0; mi < 2; mi++) {
                    mma_bf16(acc[mi][np * 2 + 0], ah[mi], bl + 0);
                    mma_bf16(acc[mi][np * 2 + 1], ah[mi], bl + 2);
                }
            }
        }
        __syncthreads();
    }

    // epilogue: direct fp32 stores
    int g = lane >> 2, tig = lane & 3;
#pragma unroll
    for (int mi = 0; mi < 2; mi++) {
#pragma unroll
        for (int ni = 0; ni < 8; ni++) {
            int mrow = wm + mi * 16 + g;
            int ncol = wn + ni * 8 + tig * 2;
            float2 v0; v0.x = acc[mi][ni][0]; v0.y = acc[mi][ni][1];
            float2 v1; v1.x = acc[mi][ni][2]; v1.y = acc[mi][ni][3];
            *reinterpret_cast<float2*>(&pC[(size_t)mrow * Tn + ncol]) = v0;
            *reinterpret_cast<float2*>(&pC[(size_t)(mrow + 8) * Tn + ncol]) = v1;
        }
    }
}

// ===================== split kernels =====================
__global__ __launch_bounds__(256)
void split_k(const float4* __restrict__ in, __nv_bfloat162* __restrict__ hi,
             __nv_bfloat162* __restrict__ lo, int n4)
{
    int i = blockIdx.x * 256 + threadIdx.x;
    if (i >= n4) return;
    float4 v = in[i];
    __nv_bfloat16 h0 = __float2bfloat16_rn(v.x), h1 = __float2bfloat16_rn(v.y);
    __nv_bfloat16 h2 = __float2bfloat16_rn(v.z), h3 = __float2bfloat16_rn(v.w);
    __nv_bfloat16 l0 = __float2bfloat16_rn(v.x - __bfloat162float(h0));
    __nv_bfloat16 l1 = __float2bfloat16_rn(v.y - __bfloat162float(h1));
    __nv_bfloat16 l2 = __float2bfloat16_rn(v.z - __bfloat162float(h2));
    __nv_bfloat16 l3 = __float2bfloat16_rn(v.w - __bfloat162float(h3));
    __nv_bfloat162 a; a.x = h0; a.y = h1;
    __nv_bfloat162 b; b.x = h2; b.y = h3;
    hi[2 * i] = a; hi[2 * i + 1] = b;
    a.x = l0; a.y = l1; b.x = l2; b.y = l3;
    lo[2 * i] = a; lo[2 * i + 1] = b;
}

// transpose + split: out[z][c][r] = in[z][r][c]
__global__ __launch_bounds__(256)
void splitT_k(const float* __restrict__ in, __nv_bfloat16* __restrict__ hi,
              __nv_bfloat16* __restrict__ lo)
{
    __shared__ float t[32][33];
    size_t zoff = (size_t)blockIdx.z * Tn * Tn;
    in += zoff; hi += zoff; lo += zoff;
    int x = blockIdx.x * 32, y = blockIdx.y * 32;
    int tx = threadIdx.x & 31, ty = threadIdx.x >> 5;   // 32 x 8
#pragma unroll
    for (int i = 0; i < 4; i++)
        t[ty + i * 8][tx] = in[(size_t)(y + ty + i * 8) * Tn + x + tx];
    __syncthreads();
#pragma unroll
    for (int i = 0; i < 4; i++) {
        float v = t[tx][ty + i * 8];
        __nv_bfloat16 h = __float2bfloat16_rn(v);
        __nv_bfloat16 l = __float2bfloat16_rn(v - __bfloat162float(h));
        size_t o = (size_t)(x + ty + i * 8) * Tn + y + tx;
        hi[o] = h; lo[o] = l;
    }
}

// =====================================================================
// 128x128 tile SGEMM (from passing baseline)
// =====================================================================
template<bool TRANSB>
__global__ __launch_bounds__(256)
void gemm128_k(const float* __restrict__ A, const float* __restrict__ B,
               const float* __restrict__ bias, const int* __restrict__ mask,
               float* __restrict__ C,
               int K, int lda, int ldb, int ldc,
               long long sA1, long long sA2, long long sB1, long long sB2,
               long long sC1, long long sC2,
               int Hdiv, int maskStride, float alpha, int relu)
{
    int z  = blockIdx.z;
    int zb = z / Hdiv, zh = z % Hdiv;
    A += zb * sA1 + zh * sA2;
    B += zb * sB1 + zh * sB2;
    C += zb * sC1 + zh * sC2;
    if (mask) mask += (long long)zb * maskStride;

    __shared__ float As[8][132];
    __shared__ float Bs[8][132];

    int tid = threadIdx.x;
    int m0 = blockIdx.y * 128, n0 = blockIdx.x * 128;

    int ar = tid >> 1;
    int ac = (tid & 1) << 2;
    int br = tid >> 5;
    int bc = (tid & 31) << 2;

    int tx = tid & 15, ty = tid >> 4;

    float acc[8][8] = {};

    for (int k0 = 0; k0 < K; k0 += 8) {
        float4 av = *reinterpret_cast<const float4*>(&A[(size_t)(m0 + ar) * lda + k0 + ac]);
        As[ac + 0][ar] = av.x; As[ac + 1][ar] = av.y;
        As[ac + 2][ar] = av.z; As[ac + 3][ar] = av.w;
        if (TRANSB) {
            float4 bv = *reinterpret_cast<const float4*>(&B[(size_t)(n0 + ar) * ldb + k0 + ac]);
            Bs[ac + 0][ar] = bv.x; Bs[ac + 1][ar] = bv.y;
            Bs[ac + 2][ar] = bv.z; Bs[ac + 3][ar] = bv.w;
        } else {
            float4 bv = *reinterpret_cast<const float4*>(&B[(size_t)(k0 + br) * ldb + n0 + bc]);
            *reinterpret_cast<float4*>(&Bs[br][bc]) = bv;
        }
        __syncthreads();
#pragma unroll
        for (int kk = 0; kk < 8; kk++) {
            float a0[4], a1[4], b0[4], b1[4];
            *reinterpret_cast<float4*>(a0) = *reinterpret_cast<const float4*>(&As[kk][ty << 2]);
            *reinterpret_cast<float4*>(a1) = *reinterpret_cast<const float4*>(&As[kk][(ty << 2) + 64]);
            *reinterpret_cast<float4*>(b0) = *reinterpret_cast<const float4*>(&Bs[kk][tx << 2]);
            *reinterpret_cast<float4*>(b1) = *reinterpret_cast<const float4*>(&Bs[kk][(tx << 2) + 64]);
#pragma unroll
            for (int i = 0; i < 4; i++)
#pragma unroll
                for (int j = 0; j < 4; j++) {
                    acc[i][j]         += a0[i] * b0[j];
                    acc[i][j + 4]     += a0[i] * b1[j];
                    acc[i + 4][j]     += a1[i] * b0[j];
                    acc[i + 4][j + 4] += a1[i] * b1[j];
                }
        }
        __syncthreads();
    }

#pragma unroll
    for (int ii = 0; ii < 8; ii++) {
        int mi = m0 + (ty << 2) + ((ii < 4) ? ii : (60 + ii));
        size_t rowoff = (size_t)mi * ldc;
#pragma unroll
        for (int jj = 0; jj < 8; jj++) {
            int col = n0 + (tx << 2) + ((jj < 4) ? jj : (60 + jj));
            float v = acc[ii][jj] * alpha;
            if (bias) v += bias[col];
            if (relu) v = fmaxf(v, 0.f);
            if (mask && mask[col] == 0) v = 1e-32f;
            C[rowoff + col] = v;
        }
    }
}

// =====================================================================
// 64x64 tile SGEMM (att@V, N=64)
// =====================================================================
#define TILE 64
#define BKs  16

template<bool TRANSB>
__global__ __launch_bounds__(256)
void gemm_k(const float* __restrict__ A, const float* __restrict__ B,
            const float* __restrict__ bias, const int* __restrict__ mask,
            float* __restrict__ C,
            int K, int lda, int ldb, int ldc,
            long long sA1, long long sA2, long long sB1, long long sB2,
            long long sC1, long long sC2,
            int Hdiv, int maskStride, float alpha, int relu)
{
    int z  = blockIdx.z;
    int zb = z / Hdiv, zh = z % Hdiv;
    A += zb * sA1 + zh * sA2;
    B += zb * sB1 + zh * sB2;
    C += zb * sC1 + zh * sC2;
    if (mask) mask += (long long)zb * maskStride;

    __shared__ float As[BKs][TILE + 4];
    __shared__ float Bs[BKs][TILE + 4];

    int tid = threadIdx.x;
    int tx = tid & 15, ty = tid >> 4;
    int m0 = blockIdx.y * TILE, n0 = blockIdx.x * TILE;
    int lr = tid >> 2;
    int lc = (tid & 3) << 2;

    float acc[4][4] = {};

    for (int k0 = 0; k0 < K; k0 += BKs) {
        float4 av = *reinterpret_cast<const float4*>(&A[(size_t)(m0 + lr) * lda + k0 + lc]);
        As[lc + 0][lr] = av.x; As[lc + 1][lr] = av.y;
        As[lc + 2][lr] = av.z; As[lc + 3][lr] = av.w;
        if (TRANSB) {
            float4 bv = *reinterpret_cast<const float4*>(&B[(size_t)(n0 + lr) * ldb + k0 + lc]);
            Bs[lc + 0][lr] = bv.x; Bs[lc + 1][lr] = bv.y;
            Bs[lc + 2][lr] = bv.z; Bs[lc + 3][lr] = bv.w;
        } else {
            int brw = tid >> 4;
            int bcl = (tid & 15) << 2;
            float4 bv = *reinterpret_cast<const float4*>(&B[(size_t)(k0 + brw) * ldb + n0 + bcl]);
            *reinterpret_cast<float4*>(&Bs[brw][bcl]) = bv;
        }
        __syncthreads();
#pragma unroll
        for (int kk = 0; kk < BKs; kk++) {
            float4 a4 = *reinterpret_cast<const float4*>(&As[kk][ty << 2]);
            float4 b4 = *reinterpret_cast<const float4*>(&Bs[kk][tx << 2]);
            float ar[4] = {a4.x, a4.y, a4.z, a4.w};
            float br[4] = {b4.x, b4.y, b4.z, b4.w};
#pragma unroll
            for (int i = 0; i < 4; i++)
#pragma unroll
                for (int j = 0; j < 4; j++) acc[i][j] += ar[i] * br[j];
        }
        __syncthreads();
    }

#pragma unroll
    for (int i = 0; i < 4; i++) {
        size_t rowoff = (size_t)(m0 + (ty << 2) + i) * ldc;
#pragma unroll
        for (int j = 0; j < 4; j++) {
            int col = n0 + (tx << 2) + j;
            float v = acc[i][j] * alpha;
            if (bias) v += bias[col];
            if (relu) v = fmaxf(v, 0.f);
            if (mask && mask[col] == 0) v = 1e-32f;
            C[rowoff + col] = v;
        }
    }
}

// ---------------- row softmax over 1024 cols, in place ----------------
__global__ __launch_bounds__(256)
void softmax_k(float* __restrict__ P)
{
    __shared__ float sdata[8];
    size_t row = blockIdx.x;
    float4* p = reinterpret_cast<float4*>(P + row * (size_t)Tn);
    int tid = threadIdx.x;
    float4 v = p[tid];
    float m = fmaxf(fmaxf(v.x, v.y), fmaxf(v.z, v.w));
#pragma unroll
    for (int o = 16; o; o >>= 1) m = fmaxf(m, __shfl_xor_sync(0xffffffffu, m, o));
    if ((tid & 31) == 0) sdata[tid >> 5] = m;
    __syncthreads();
    if (tid == 0) {
        float t = sdata[0];
#pragma unroll
        for (int i = 1; i < 8; i++) t = fmaxf(t, sdata[i]);
        sdata[0] = t;
    }
    __syncthreads();
    m = sdata[0];
    v.x = expf(v.x - m); v.y = expf(v.y - m);
    v.z = expf(v.z - m); v.w = expf(v.w - m);
    float s = v.x + v.y + v.z + v.w;
#pragma unroll
    for (int o = 16; o; o >>= 1) s += __shfl_xor_sync(0xffffffffu, s, o);
    __syncthreads();
    if ((tid & 31) == 0) sdata[tid >> 5] = s;
    __syncthreads();
    if (tid == 0) {
        float t = 0.f;
#pragma unroll
        for (int i = 0; i < 8; i++) t += sdata[i];
        sdata[0] = t;
    }
    __syncthreads();
    float inv = 1.f / sdata[0];
    v.x *= inv; v.y *= inv; v.z *= inv; v.w *= inv;
    p[tid] = v;
}

// ---------------- out = LayerNorm(X + Y) * g + b ----------------
__global__ __launch_bounds__(256)
void add_ln_k(const float* __restrict__ X, const float* __restrict__ Y,
              const float* __restrict__ g, const float* __restrict__ b,
              float* __restrict__ out)
{
    __shared__ float s1[8], s2[8];
    size_t row = (size_t)blockIdx.x * Dn;
    int tid = threadIdx.x;
    float4 x = *reinterpret_cast<const float4*>(X + row + tid * 4);
    float4 y = *reinterpret_cast<const float4*>(Y + row + tid * 4);
    float4 v; v.x = x.x + y.x; v.y = x.y + y.y; v.z = x.z + y.z; v.w = x.w + y.w;
    float sum = v.x + v.y + v.z + v.w;
    float sq  = v.x*v.x + v.y*v.y + v.z*v.z + v.w*v.w;
#pragma unroll
    for (int o = 16; o; o >>= 1) {
        sum += __shfl_xor_sync(0xffffffffu, sum, o);
        sq  += __shfl_xor_sync(0xffffffffu, sq,  o);
    }
    if ((tid & 31) == 0) { s1[tid >> 5] = sum; s2[tid >> 5] = sq; }
    __syncthreads();
    if (tid == 0) {
        float a = 0.f, c = 0.f;
#pragma unroll
        for (int i = 0; i < 8; i++) { a += s1[i]; c += s2[i]; }
        s1[0] = a; s2[0] = c;
    }
    __syncthreads();
    float mean = s1[0] * (1.f / Dn);
    float var  = s2[0] * (1.f / Dn) - mean * mean;
    float inv  = rsqrtf(var + 1e-5f);
    float4 gg = *reinterpret_cast<const float4*>(g + tid * 4);
    float4 bb = *reinterpret_cast<const float4*>(b + tid * 4);
    float4 o;
    o.x = (v.x - mean) * inv * gg.x + bb.x;
    o.y = (v.y - mean) * inv * gg.y + bb.y;
    o.z = (v.z - mean) * inv * gg.z + bb.z;
    o.w = (v.w - mean) * inv * gg.w + bb.w;
    *reinterpret_cast<float4*>(out + row + tid * 4) = o;
}

// ---------------- host side ----------------
static void launch_gemm128(bool transb,
                           const float* A, const float* B, const float* bias, const int* mask,
                           float* C, int M, int N, int K, int lda, int ldb, int ldc,
                           long long sA1, long long sA2, long long sB1, long long sB2,
                           long long sC1, long long sC2,
                           int Hdiv, int maskStride, float alpha, int relu, int batches)
{
    dim3 grid(N / 128, M / 128, batches), block(256);
    if (transb)
        gemm128_k<true><<<grid, block>>>(A, B, bias, mask, C, K, lda, ldb, ldc,
                                         sA1, sA2, sB1, sB2, sC1, sC2, Hdiv, maskStride, alpha, relu);
    else
        gemm128_k<false><<<grid, block>>>(A, B, bias, mask, C, K, lda, ldb, ldc,
                                          sA1, sA2, sB1, sB2, sC1, sC2, Hdiv, maskStride, alpha, relu);
}

static void launch_gemm64(bool transb,
                          const float* A, const float* B, const float* bias, const int* mask,
                          float* C, int M, int N, int K, int lda, int ldb, int ldc,
                          long long sA1, long long sA2, long long sB1, long long sB2,
                          long long sC1, long long sC2,
                          int Hdiv, int maskStride, float alpha, int relu, int batches)
{
    dim3 grid(N / TILE, M / TILE, batches), block(256);
    if (transb)
        gemm_k<true><<<grid, block>>>(A, B, bias, mask, C, K, lda, ldb, ldc,
                                      sA1, sA2, sB1, sB2, sC1, sC2, Hdiv, maskStride, alpha, relu);
    else
        gemm_k<false><<<grid, block>>>(A, B, bias, mask, C, K, lda, ldb, ldc,
                                       sA1, sA2, sB1, sB2, sC1, sC2, Hdiv, maskStride, alpha, relu);
}

extern "C" void kernel_launch(void* const* d_in, const int* in_sizes, int n_in,
                              void* d_out, int out_size)
{
    const float* src = (const float*)d_in[0];
    const float* aux = (const float*)d_in[1];
    const float* Wu  = (const float*)d_in[2];
    const float* bu  = (const float*)d_in[3];
    const float* Wv  = (const float*)d_in[4];
    const float* bv  = (const float*)d_in[5];
    const float* Wo  = (const float*)d_in[6];
    const float* bo  = (const float*)d_in[7];
    const float* W1  = (const float*)d_in[8];
    const float* b1  = (const float*)d_in[9];
    const float* W2  = (const float*)d_in[10];
    const float* b2  = (const float*)d_in[11];
    const float* g1  = (const float*)d_in[12];
    const float* be1 = (const float*)d_in[13];
    const float* g2  = (const float*)d_in[14];
    const float* be2 = (const float*)d_in[15];
    const int* src_mask = (const int*)d_in[16];
    const int* aux_mask = (const int*)d_in[17];
    float* out = (float*)d_out;

    float *qkv_u, *qkv_v, *sim1, *sim2, *comb, *head, *proj, *o1, *ffh;
    __nv_bfloat16 *s1h, *s1l, *s2h, *s2l, *s1th, *s1tl, *s2th, *s2tl;
    cudaGetSymbolAddress((void**)&qkv_u, g_qkv_u);
    cudaGetSymbolAddress((void**)&qkv_v, g_qkv_v);
    cudaGetSymbolAddress((void**)&sim1,  g_sim1);
    cudaGetSymbolAddress((void**)&sim2,  g_sim2);
    cudaGetSymbolAddress((void**)&comb,  g_comb);
    cudaGetSymbolAddress((void**)&head,  g_head);
    cudaGetSymbolAddress((void**)&proj,  g_proj);
    cudaGetSymbolAddress((void**)&o1,    g_o1);
    cudaGetSymbolAddress((void**)&ffh,   g_ffh);
    cudaGetSymbolAddress((void**)&s1h,  g_s1h);
    cudaGetSymbolAddress((void**)&s1l,  g_s1l);
    cudaGetSymbolAddress((void**)&s2h,  g_s2h);
    cudaGetSymbolAddress((void**)&s2l,  g_s2l);
    cudaGetSymbolAddress((void**)&s1th, g_s1th);
    cudaGetSymbolAddress((void**)&s1tl, g_s1tl);
    cudaGetSymbolAddress((void**)&s2th, g_s2th);
    cudaGetSymbolAddress((void**)&s2tl, g_s2tl);

    cudaFuncSetAttribute(comb_mma_k, cudaFuncAttributeMaxDynamicSharedMemorySize, SMEM_DYN);

    const long long sQKV = (long long)Tn * 3 * An;
    const long long sHT2 = (long long)Hn * Tn * Tn;
    const long long sT2  = (long long)Tn * Tn;
    const long long sTA  = (long long)Tn * An;

    // ---- QKV projections
    launch_gemm128(false, src, Wu, bu, nullptr, qkv_u, BTn, 3 * An, Dn, Dn, 3 * An, 3 * An,
                   0, 0, 0, 0, 0, 0, 1, 0, 1.f, 0, 1);
    launch_gemm128(false, aux, Wv, bv, nullptr, qkv_v, BTn, 3 * An, Dn, Dn, 3 * An, 3 * An,
                   0, 0, 0, 0, 0, 0, 1, 0, 1.f, 0, 1);

    // ---- sim1 / sim2 (masked, scaled)
    launch_gemm128(true, qkv_u, qkv_v + An, nullptr, aux_mask, sim1,
                   Tn, Tn, HDn, 3 * An, 3 * An, Tn,
                   sQKV, HDn, sQKV, HDn, sHT2, sT2, Hn, Tn, 0.125f, 0, ZHn);
    launch_gemm128(true, qkv_v, qkv_u + An, nullptr, src_mask, sim2,
                   Tn, Tn, HDn, 3 * An, 3 * An, Tn,
                   sQKV, HDn, sQKV, HDn, sHT2, sT2, Hn, Tn, 0.125f, 0, ZHn);

    // ---- bf16 hi/lo splits (row-major + transposed layouts)
    {
        int n4 = (int)(SIMELEMS / 4);
        int blocks = (n4 + 255) / 256;
        split_k<<<blocks, 256>>>((const float4*)sim1, (__nv_bfloat162*)s1h, (__nv_bfloat162*)s1l, n4);
        split_k<<<blocks, 256>>>((const float4*)sim2, (__nv_bfloat162*)s2h, (__nv_bfloat162*)s2l, n4);
        splitT_k<<<dim3(32, 32, ZHn), 256>>>(sim1, s1th, s1tl);
        splitT_k<<<dim3(32, 32, ZHn), 256>>>(sim2, s2th, s2tl);
    }

    dim3 cgrid(8, 8, ZHn);

    // ================= stream U =================
    comb_mma_k<<<cgrid, 256, SMEM_DYN>>>(s1h, s1l, s2th, s2tl, comb);   // sim1 @ sim2
    softmax_k<<<ZHn * Tn, 256>>>(comb);
    launch_gemm64(false, comb, qkv_u + 2 * An, nullptr, nullptr, head,
                  Tn, HDn, Tn, Tn, 3 * An, An,
                  sHT2, sT2, sQKV, HDn, sTA, HDn, Hn, 0, 1.f, 0, ZHn);
    launch_gemm128(false, head, Wo, bo, nullptr, proj, BTn, Dn, An, An, Dn, Dn,
                   0, 0, 0, 0, 0, 0, 1, 0, 1.f, 0, 1);
    add_ln_k<<<BTn, 256>>>(src, proj, g1, be1, o1);
    launch_gemm128(false, o1, W1, b1, nullptr, ffh, BTn, Fn, Dn, Dn, Fn, Fn,
                   0, 0, 0, 0, 0, 0, 1, 0, 1.f, 1, 1);
    launch_gemm128(false, ffh, W2, b2, nullptr, proj, BTn, Dn, Fn, Fn, Dn, Dn,
                   0, 0, 0, 0, 0, 0, 1, 0, 1.f, 0, 1);
    add_ln_k<<<BTn, 256>>>(o1, proj, g2, be2, out);

    // ================= stream V =================
    comb_mma_k<<<cgrid, 256, SMEM_DYN>>>(s2h, s2l, s1th, s1tl, comb);   // sim2 @ sim1
    softmax_k<<<ZHn * Tn, 256>>>(comb);
    launch_gemm64(false, comb, qkv_v + 2 * An, nullptr, nullptr, head,
                  Tn, HDn, Tn, Tn, 3 * An, An,
                  sHT2, sT2, sQKV, HDn, sTA, HDn, Hn, 0, 1.f, 0, ZHn);
    launch_gemm128(false, head, Wo, bo, nullptr, proj, BTn, Dn, An, An, Dn, Dn,
                   0, 0, 0, 0, 0, 0, 1, 0, 1.f, 0, 1);
    add_ln_k<<<BTn, 256>>>(aux, proj, g1, be1, o1);
    launch_gemm128(false, o1, W1, b1, nullptr, ffh, BTn, Fn, Dn, Dn, Fn, Fn,
                   0, 0, 0, 0, 0, 0, 1, 0, 1.f, 1, 1);
    launch_gemm128(false, ffh, W2, b2, nullptr, proj, BTn, Dn, Fn, Fn, Dn, Dn,
                   0, 0, 0, 0, 0, 0, 1, 0, 1.f, 0, 1);
    add_ln_k<<<BTn, 256>>>(o1, proj, g2, be2, out + (size_t)BTn * Dn);
}

// round 6
// speedup vs baseline: 2.7494x; 2.0368x over previous
#include <cuda_runtime.h>
#include <cuda_bf16.h>
#include <math.h>
#include <stdint.h>

typedef __nv_bfloat16 bf16;
typedef __nv_bfloat162 bf162;

// Problem constants
#define Tn   1024
#define Dn   1024
#define Hn   16
#define HDn  64
#define An   1024
#define Fn   4096
#define Bn   2
#define BTn  (Bn*Tn)       // 2048
#define ZHn  (Bn*Hn)       // 32

// ---------------- scratch pool (allocation-free) ----------------
#define N_T2   ((size_t)ZHn*Tn*Tn)      // 33,554,432
#define N_BTD  ((size_t)BTn*Dn)         // 2,097,152
#define N_QKV  ((size_t)BTn*3*An)       // 6,291,456
#define N_W3   ((size_t)3*An*Dn)        // 3,145,728
#define N_WF   ((size_t)Fn*Dn)          // 4,194,304
#define N_BTF  ((size_t)BTn*Fn)         // 8,388,608
#define N_VT   ((size_t)ZHn*HDn*Tn)     // 2,097,152

// byte offsets into the pool
static constexpr size_t O_COMB = 0;
static constexpr size_t O_PROJ = O_COMB + N_T2*4;
static constexpr size_t O_O1   = O_PROJ + N_BTD*4;
static constexpr size_t O_SRCH = O_O1   + N_BTD*4;
static constexpr size_t O_SRCL = O_SRCH + N_BTD*2;
static constexpr size_t O_AUXH = O_SRCL + N_BTD*2;
static constexpr size_t O_AUXL = O_AUXH + N_BTD*2;
static constexpr size_t O_WUTH = O_AUXL + N_BTD*2;
static constexpr size_t O_WUTL = O_WUTH + N_W3*2;
static constexpr size_t O_WVTH = O_WUTL + N_W3*2;
static constexpr size_t O_WVTL = O_WVTH + N_W3*2;
static constexpr size_t O_WOTH = O_WVTL + N_W3*2;
static constexpr size_t O_WOTL = O_WOTH + (size_t)An*Dn*2;
static constexpr size_t O_W1TH = O_WOTL + (size_t)An*Dn*2;
static constexpr size_t O_W1TL = O_W1TH + N_WF*2;
static constexpr size_t O_W2TH = O_W1TL + N_WF*2;
static constexpr size_t O_W2TL = O_W2TH + N_WF*2;
static constexpr size_t O_QUH  = O_W2TL + N_WF*2;
static constexpr size_t O_QUL  = O_QUH  + N_QKV*2;
static constexpr size_t O_QVH  = O_QUL  + N_QKV*2;
static constexpr size_t O_QVL  = O_QVH  + N_QKV*2;
static constexpr size_t O_S1H  = O_QVL  + N_QKV*2;
static constexpr size_t O_S1L  = O_S1H  + N_T2*2;
static constexpr size_t O_S2H  = O_S1L  + N_T2*2;
static constexpr size_t O_S2L  = O_S2H  + N_T2*2;
static constexpr size_t O_S1TH = O_S2L  + N_T2*2;
static constexpr size_t O_S1TL = O_S1TH + N_T2*2;
static constexpr size_t O_S2TH = O_S1TL + N_T2*2;
static constexpr size_t O_S2TL = O_S2TH + N_T2*2;
static constexpr size_t O_ATTH = O_S2TL + N_T2*2;
static constexpr size_t O_ATTL = O_ATTH + N_T2*2;
static constexpr size_t O_VTUH = O_ATTL + N_T2*2;
static constexpr size_t O_VTUL = O_VTUH + N_VT*2;
static constexpr size_t O_VTVH = O_VTUL + N_VT*2;
static constexpr size_t O_VTVL = O_VTVH + N_VT*2;
static constexpr size_t O_HDH  = O_VTVL + N_VT*2;
static constexpr size_t O_HDL  = O_HDH  + (size_t)BTn*An*2;
static constexpr size_t O_O1H  = O_HDL  + (size_t)BTn*An*2;
static constexpr size_t O_O1L  = O_O1H  + N_BTD*2;
static constexpr size_t O_FFHH = O_O1L  + N_BTD*2;
static constexpr size_t O_FFHL = O_FFHH + N_BTF*2;
static constexpr size_t POOL_BYTES = O_FFHL + N_BTF*2;

__device__ __align__(1024) unsigned char g_pool[POOL_BYTES];

// ===================== portable PTX helpers (sm_80+) =====================
__device__ __forceinline__ uint32_t smem_u32(const void* p) {
    uint32_t a;
    asm("{ .reg .u64 t; cvta.to.shared.u64 t, %1; cvt.u32.u64 %0, t; }" : "=r"(a) : "l"(p));
    return a;
}
#define SW128(off) ((off) ^ (((off) >> 3) & 0x70))

__device__ __forceinline__ void cp_async16(uint32_t saddr, const void* gptr) {
    asm volatile("cp.async.cg.shared.global [%0], [%1], 16;" :: "r"(saddr), "l"(gptr) : "memory");
}
__device__ __forceinline__ void cp_commit() {
    asm volatile("cp.async.commit_group;" ::: "memory");
}
template<int N>
__device__ __forceinline__ void cp_wait() {
    asm volatile("cp.async.wait_group %0;" :: "n"(N) : "memory");
}
__device__ __forceinline__ void ldsm4(uint32_t* r, uint32_t addr) {
    asm volatile("ldmatrix.sync.aligned.m8n8.x4.shared.b16 {%0,%1,%2,%3}, [%4];"
                 : "=r"(r[0]), "=r"(r[1]), "=r"(r[2]), "=r"(r[3]) : "r"(addr));
}
__device__ __forceinline__ void mma_bf16(float* c, const uint32_t* a, const uint32_t* b) {
    asm volatile("mma.sync.aligned.m16n8k16.row.col.f32.bf16.bf16.f32 "
                 "{%0,%1,%2,%3}, {%4,%5,%6,%7}, {%8,%9}, {%0,%1,%2,%3};"
                 : "+f"(c[0]), "+f"(c[1]), "+f"(c[2]), "+f"(c[3])
                 : "r"(a[0]), "r"(a[1]), "r"(a[2]), "r"(a[3]), "r"(b[0]), "r"(b[1]));
}
__device__ __forceinline__ void split2(float v, bf16& h, bf16& l) {
    h = __float2bfloat16_rn(v);
    l = __float2bfloat16_rn(v - __bfloat162float(h));
}

// ===================== generic bf16x3 HMMA GEMM =====================
// C/O[m,n] = epilogue( alpha * (Ah+Al)[m,:] . (Bh+Bl)[n,:] )   (lo*lo dropped)
// A: [m][k] bf16 pair, row stride lda. B: [n][k] bf16 pair, row stride ldb.
// Outputs: optional fp32 C, optional bf16 hi/lo pair Oh/Ol (same ldc/offsets).
// Batched over blockIdx.z: off = (z/Hdiv)*s1 + (z%Hdiv)*s2.
template<int BNT>
__global__ __launch_bounds__(256, 1)
void hgemm_k(const bf16* __restrict__ Ah, const bf16* __restrict__ Al,
             const bf16* __restrict__ Bh, const bf16* __restrict__ Bl,
             float* __restrict__ C, bf16* __restrict__ Oh, bf16* __restrict__ Ol,
             int K, int lda, int ldb, int ldc,
             long long sA1, long long sA2, long long sB1, long long sB2,
             long long sC1, long long sC2, int Hdiv,
             const float* __restrict__ bias, const int* __restrict__ mask,
             int maskStride, float alpha, int relu)
{
    constexpr int ABYTES = 16384;
    constexpr int BBYTES = BNT * 128;
    constexpr int SS = 2 * ABYTES + 2 * BBYTES;
    extern __shared__ char smraw[];
    uint32_t raw = smem_u32(smraw);
    uint32_t base = (raw + 1023u) & ~1023u;

    int tid = threadIdx.x, wid = tid >> 5, lane = tid & 31;
    int z = blockIdx.z, zb = z / Hdiv, zh = z % Hdiv;
    int m0 = blockIdx.y * 128, n0 = blockIdx.x * BNT;
    Ah += zb * sA1 + zh * sA2 + (size_t)m0 * lda;
    Al += zb * sA1 + zh * sA2 + (size_t)m0 * lda;
    Bh += zb * sB1 + zh * sB2 + (size_t)n0 * ldb;
    Bl += zb * sB1 + zh * sB2 + (size_t)n0 * ldb;
    long long coff = zb * sC1 + zh * sC2 + (long long)m0 * ldc + n0;
    const int* pmask = mask ? mask + (size_t)zb * maskStride + n0 : nullptr;
    const float* pbias = bias ? bias + n0 : nullptr;

    auto load_stage = [&](int s, int kc) {
        uint32_t sb = base + (uint32_t)s * SS;
#pragma unroll
        for (int i = 0; i < 4; i++) {
            int q = tid + i * 256;
            int r = q >> 3, cb = q & 7;
            uint32_t sw = SW128((uint32_t)(r * 128 + cb * 16));
            size_t go = (size_t)r * lda + kc * 64 + cb * 8;
            cp_async16(sb + sw, Ah + go);
            cp_async16(sb + ABYTES + sw, Al + go);
        }
#pragma unroll
        for (int i = 0; i < BNT / 32; i++) {
            int q = tid + i * 256;
            int r = q >> 3, cb = q & 7;
            uint32_t sw = SW128((uint32_t)(r * 128 + cb * 16));
            size_t go = (size_t)r * ldb + kc * 64 + cb * 8;
            cp_async16(sb + 2 * ABYTES + sw, Bh + go);
            cp_async16(sb + 2 * ABYTES + BBYTES + sw, Bl + go);
        }
        cp_commit();
    };

    int wm = (wid >> 1) * 32;
    int wn = (wid & 1) * (BNT / 2);

    float acc[2][BNT / 16][4];
#pragma unroll
    for (int a = 0; a < 2; a++)
#pragma unroll
        for (int b = 0; b < BNT / 16; b++)
#pragma unroll
            for (int c = 0; c < 4; c++) acc[a][b][c] = 0.f;

    int a_row = wm + (lane & 15);
    int a_cb  = (lane >> 4) * 16;
    int b_row = wn + (lane & 7) + ((lane >> 4) << 3);
    int b_cb  = ((lane >> 3) & 1) * 16;

    load_stage(0, 0);
    int NCH = K / 64;

    for (int c = 0; c < NCH; c++) {
        if (c + 1 < NCH) { load_stage((c + 1) & 1, c + 1); cp_wait<1>(); }
        else             { cp_wait<0>(); }
        __syncthreads();

        uint32_t sb = base + (uint32_t)(c & 1) * SS;
        uint32_t sAh = sb, sAl = sb + ABYTES;
        uint32_t sBh = sb + 2 * ABYTES, sBl = sb + 2 * ABYTES + BBYTES;

#pragma unroll
        for (int ks = 0; ks < 4; ks++) {
            uint32_t ah[2][4], al[2][4];
            int acol = ks * 32 + a_cb;
#pragma unroll
            for (int mi = 0; mi < 2; mi++) {
                int sw = SW128((a_row + mi * 16) * 128 + acol);
                ldsm4(ah[mi], sAh + sw);
                ldsm4(al[mi], sAl + sw);
            }
            int bcol = ks * 32 + b_cb;
#pragma unroll
            for (int np = 0; np < BNT / 32; np++) {
                int sw = SW128((b_row + np * 16) * 128 + bcol);
                uint32_t bh[4], bl[4];
                ldsm4(bh, sBh + sw);
#pragma unroll
                for (int mi = 0; mi < 2; mi++) {
                    mma_bf16(acc[mi][np * 2 + 0], ah[mi], bh + 0);
                    mma_bf16(acc[mi][np * 2 + 1], ah[mi], bh + 2);
                    mma_bf16(acc[mi][np * 2 + 0], al[mi], bh + 0);
                    mma_bf16(acc[mi][np * 2 + 1], al[mi], bh + 2);
                }
                ldsm4(bl, sBl + sw);
#pragma unroll
                for (int mi = 0; mi < 2; mi++) {
                    mma_bf16(acc[mi][np * 2 + 0], ah[mi], bl + 0);
                    mma_bf16(acc[mi][np * 2 + 1], ah[mi], bl + 2);
                }
            }
        }
        __syncthreads();
    }

    // epilogue
    int g = lane >> 2, tig = lane & 3;
#pragma unroll
    for (int mi = 0; mi < 2; mi++) {
#pragma unroll
        for (int ni = 0; ni < BNT / 16; ni++) {
            int mrow = wm + mi * 16 + g;
            int ncol = wn + ni * 8 + tig * 2;
            float v0 = acc[mi][ni][0] * alpha;
            float v1 = acc[mi][ni][1] * alpha;
            float v2 = acc[mi][ni][2] * alpha;
            float v3 = acc[mi][ni][3] * alpha;
            if (pbias) {
                float b0 = pbias[ncol], b1 = pbias[ncol + 1];
                v0 += b0; v1 += b1; v2 += b0; v3 += b1;
            }
            if (relu) {
                v0 = fmaxf(v0, 0.f); v1 = fmaxf(v1, 0.f);
                v2 = fmaxf(v2, 0.f); v3 = fmaxf(v3, 0.f);
            }
            if (pmask) {
                if (pmask[ncol] == 0)     { v0 = 1e-32f; v2 = 1e-32f; }
                if (pmask[ncol + 1] == 0) { v1 = 1e-32f; v3 = 1e-32f; }
            }
            long long o0 = coff + (long long)mrow * ldc + ncol;
            long long o1 = o0 + (long long)8 * ldc;
            if (C) {
                float2 f0; f0.x = v0; f0.y = v1;
                float2 f1; f1.x = v2; f1.y = v3;
                *reinterpret_cast<float2*>(&C[o0]) = f0;
                *reinterpret_cast<float2*>(&C[o1]) = f1;
            }
            if (Oh) {
                bf16 h0, l0, h1, l1, h2, l2, h3, l3;
                split2(v0, h0, l0); split2(v1, h1, l1);
                split2(v2, h2, l2); split2(v3, h3, l3);
                bf162 hv0; hv0.x = h0; hv0.y = h1;
                bf162 hv1; hv1.x = h2; hv1.y = h3;
                bf162 lv0; lv0.x = l0; lv0.y = l1;
                bf162 lv1; lv1.x = l2; lv1.y = l3;
                *reinterpret_cast<bf162*>(&Oh[o0]) = hv0;
                *reinterpret_cast<bf162*>(&Oh[o1]) = hv1;
                *reinterpret_cast<bf162*>(&Ol[o0]) = lv0;
                *reinterpret_cast<bf162*>(&Ol[o1]) = lv1;
            }
        }
    }
}

// ===================== comb MMA kernel (validated round 4) =====================
#define MAT_BYTES 16384
#define STAGE_BYTES (4*MAT_BYTES)
#define NCHUNK 16
#define SMEM_COMB (2*STAGE_BYTES + 1024)

__global__ __launch_bounds__(256, 1)
void comb_mma_k(const bf16* __restrict__ Ah, const bf16* __restrict__ Al,
                const bf16* __restrict__ Bh, const bf16* __restrict__ Bl,
                float* __restrict__ C)
{
    extern __shared__ char smraw[];
    uint32_t raw  = smem_u32(smraw);
    uint32_t base = (raw + 1023u) & ~1023u;

    int tid = threadIdx.x, wid = tid >> 5, lane = tid & 31;
    int z = blockIdx.z, m0 = blockIdx.y * 128, n0 = blockIdx.x * 128;
    size_t zoff = (size_t)z * Tn * Tn;
    const bf16* pAh = Ah + zoff + (size_t)m0 * Tn;
    const bf16* pAl = Al + zoff + (size_t)m0 * Tn;
    const bf16* pBh = Bh + zoff + (size_t)n0 * Tn;
    const bf16* pBl = Bl + zoff + (size_t)n0 * Tn;
    float* pC = C + zoff + (size_t)m0 * Tn + n0;

    int lr[4], lsw[4];
#pragma unroll
    for (int i = 0; i < 4; i++) {
        int q = tid + i * 256;
        lr[i]  = q >> 3;
        int c  = q & 7;
        lsw[i] = SW128(lr[i] * 128 + c * 16);
    }

    auto load_stage = [&](int s, int kc) {
        uint32_t sb = base + (uint32_t)s * STAGE_BYTES;
#pragma unroll
        for (int i = 0; i < 4; i++) {
            size_t go = (size_t)lr[i] * Tn + kc * 64 + ((tid + i * 256) & 7) * 8;
            cp_async16(sb + 0 * MAT_BYTES + lsw[i], pAh + go);
            cp_async16(sb + 1 * MAT_BYTES + lsw[i], pAl + go);
            cp_async16(sb + 2 * MAT_BYTES + lsw[i], pBh + go);
            cp_async16(sb + 3 * MAT_BYTES + lsw[i], pBl + go);
        }
        cp_commit();
    };

    int wm = (wid >> 1) * 32;
    int wn = (wid & 1) * 64;

    float acc[2][8][4];
#pragma unroll
    for (int a = 0; a < 2; a++)
#pragma unroll
        for (int b = 0; b < 8; b++)
#pragma unroll
            for (int c = 0; c < 4; c++) acc[a][b][c] = 0.f;

    int a_row = wm + (lane & 15);
    int a_cb  = (lane >> 4) * 16;
    int b_row = wn + (lane & 7) + ((lane >> 4) << 3);
    int b_cb  = ((lane >> 3) & 1) * 16;

    load_stage(0, 0);

    for (int c = 0; c < NCHUNK; c++) {
        if (c + 1 < NCHUNK) { load_stage((c + 1) & 1, c + 1); cp_wait<1>(); }
        else                { cp_wait<0>(); }
        __syncthreads();

        uint32_t sb = base + (uint32_t)(c & 1) * STAGE_BYTES;
        uint32_t sAh = sb, sAl = sb + MAT_BYTES, sBh = sb + 2 * MAT_BYTES, sBl = sb + 3 * MAT_BYTES;

#pragma unroll
        for (int ks = 0; ks < 4; ks++) {
            uint32_t ah[2][4], al[2][4];
            int acol = ks * 32 + a_cb;
#pragma unroll
            for (int mi = 0; mi < 2; mi++) {
                int sw = SW128((a_row + mi * 16) * 128 + acol);
                ldsm4(ah[mi], sAh + sw);
                ldsm4(al[mi], sAl + sw);
            }
            int bcol = ks * 32 + b_cb;
#pragma unroll
            for (int np = 0; np < 4; np++) {
                int sw = SW128((b_row + np * 16) * 128 + bcol);
                uint32_t bh[4], bl[4];
                ldsm4(bh, sBh + sw);
#pragma unroll
                for (int mi = 0; mi < 2; mi++) {
                    mma_bf16(acc[mi][np * 2 + 0], ah[mi], bh + 0);
                    mma_bf16(acc[mi][np * 2 + 1], ah[mi], bh + 2);
                    mma_bf16(acc[mi][np * 2 + 0], al[mi], bh + 0);
                    mma_bf16(acc[mi][np * 2 + 1], al[mi], bh + 2);
                }
                ldsm4(bl, sBl + sw);
#pragma unroll
                for (int mi = 0; mi < 2; mi++) {
                    mma_bf16(acc[mi][np * 2 + 0], ah[mi], bl + 0);
                    mma_bf16(acc[mi][np * 2 + 1], ah[mi], bl + 2);
                }
            }
        }
        __syncthreads();
    }

    int g = lane >> 2, tig = lane & 3;
#pragma unroll
    for (int mi = 0; mi < 2; mi++) {
#pragma unroll
        for (int ni = 0; ni < 8; ni++) {
            int mrow = wm + mi * 16 + g;
            int ncol = wn + ni * 8 + tig * 2;
            float2 v0; v0.x = acc[mi][ni][0]; v0.y = acc[mi][ni][1];
            float2 v1; v1.x = acc[mi][ni][2]; v1.y = acc[mi][ni][3];
            *reinterpret_cast<float2*>(&pC[(size_t)mrow * Tn + ncol]) = v0;
            *reinterpret_cast<float2*>(&pC[(size_t)(mrow + 8) * Tn + ncol]) = v1;
        }
    }
}

// ===================== elementwise kernels =====================
__global__ __launch_bounds__(256)
void split_k(const float4* __restrict__ in, bf162* __restrict__ hi,
             bf162* __restrict__ lo, int n4)
{
    int i = blockIdx.x * 256 + threadIdx.x;
    if (i >= n4) return;
    float4 v = in[i];
    bf16 h0, l0, h1, l1, h2, l2, h3, l3;
    split2(v.x, h0, l0); split2(v.y, h1, l1);
    split2(v.z, h2, l2); split2(v.w, h3, l3);
    bf162 a, b;
    a.x = h0; a.y = h1; b.x = h2; b.y = h3;
    hi[2 * i] = a; hi[2 * i + 1] = b;
    a.x = l0; a.y = l1; b.x = l2; b.y = l3;
    lo[2 * i] = a; lo[2 * i + 1] = b;
}

// weight transpose+split: fp32 in [R][C] -> hi/lo bf16 [C][R]
__global__ __launch_bounds__(256)
void wsplitT_k(const float* __restrict__ in, bf16* __restrict__ oh,
               bf16* __restrict__ ol, int ldin, int ldout)
{
    __shared__ float t[32][33];
    int x0 = blockIdx.x * 32, y0 = blockIdx.y * 32;
    int tx = threadIdx.x & 31, ty = threadIdx.x >> 5;
#pragma unroll
    for (int i = 0; i < 4; i++)
        t[ty + i * 8][tx] = in[(size_t)(y0 + ty + i * 8) * ldin + x0 + tx];
    __syncthreads();
#pragma unroll
    for (int i = 0; i < 4; i++) {
        float v = t[tx][ty + i * 8];
        bf16 h, l; split2(v, h, l);
        size_t o = (size_t)(x0 + ty + i * 8) * ldout + y0 + tx;
        oh[o] = h; ol[o] = l;
    }
}

// bf16 dual transpose: hi/lo [r][c] -> [c][r], batched
__global__ __launch_bounds__(256)
void btran_k(const bf16* __restrict__ inH, const bf16* __restrict__ inL,
             bf16* __restrict__ outH, bf16* __restrict__ outL,
             int ldin, int ldout,
             long long sI1, long long sI2, long long sO, int Hdiv)
{
    __shared__ bf16 th[32][34], tl[32][34];
    int z = blockIdx.z, zb = z / Hdiv, zh = z % Hdiv;
    inH += zb * sI1 + zh * sI2; inL += zb * sI1 + zh * sI2;
    outH += (size_t)z * sO; outL += (size_t)z * sO;
    int x0 = blockIdx.x * 32, y0 = blockIdx.y * 32;
    int tx = threadIdx.x & 31, ty = threadIdx.x >> 5;
#pragma unroll
    for (int i = 0; i < 4; i++) {
        size_t o = (size_t)(y0 + ty + i * 8) * ldin + x0 + tx;
        th[ty + i * 8][tx] = inH[o];
        tl[ty + i * 8][tx] = inL[o];
    }
    __syncthreads();
#pragma unroll
    for (int i = 0; i < 4; i++) {
        size_t o = (size_t)(x0 + ty + i * 8) * ldout + y0 + tx;
        outH[o] = th[tx][ty + i * 8];
        outL[o] = tl[tx][ty + i * 8];
    }
}

// row softmax over 1024 fp32 cols -> hi/lo bf16
__global__ __launch_bounds__(256)
void softmax_bf_k(const float* __restrict__ P, bf16* __restrict__ oh, bf16* __restrict__ ol)
{
    __shared__ float sdata[8];
    size_t row = blockIdx.x;
    const float4* p = reinterpret_cast<const float4*>(P + row * (size_t)Tn);
    int tid = threadIdx.x;
    float4 v = p[tid];
    float m = fmaxf(fmaxf(v.x, v.y), fmaxf(v.z, v.w));
#pragma unroll
    for (int o = 16; o; o >>= 1) m = fmaxf(m, __shfl_xor_sync(0xffffffffu, m, o));
    if ((tid & 31) == 0) sdata[tid >> 5] = m;
    __syncthreads();
    if (tid == 0) {
        float t = sdata[0];
#pragma unroll
        for (int i = 1; i < 8; i++) t = fmaxf(t, sdata[i]);
        sdata[0] = t;
    }
    __syncthreads();
    m = sdata[0];
    v.x = expf(v.x - m); v.y = expf(v.y - m);
    v.z = expf(v.z - m); v.w = expf(v.w - m);
    float s = v.x + v.y + v.z + v.w;
#pragma unroll
    for (int o = 16; o; o >>= 1) s += __shfl_xor_sync(0xffffffffu, s, o);
    __syncthreads();
    if ((tid & 31) == 0) sdata[tid >> 5] = s;
    __syncthreads();
    if (tid == 0) {
        float t = 0.f;
#pragma unroll
        for (int i = 0; i < 8; i++) t += sdata[i];
        sdata[0] = t;
    }
    __syncthreads();
    float inv = 1.f / sdata[0];
    v.x *= inv; v.y *= inv; v.z *= inv; v.w *= inv;
    bf16 h0, l0, h1, l1, h2, l2, h3, l3;
    split2(v.x, h0, l0); split2(v.y, h1, l1);
    split2(v.z, h2, l2); split2(v.w, h3, l3);
    bf162 a, b;
    size_t o0 = row * Tn + tid * 4;
    a.x = h0; a.y = h1; b.x = h2; b.y = h3;
    *reinterpret_cast<bf162*>(&oh[o0]) = a;
    *reinterpret_cast<bf162*>(&oh[o0 + 2]) = b;
    a.x = l0; a.y = l1; b.x = l2; b.y = l3;
    *reinterpret_cast<bf162*>(&ol[o0]) = a;
    *reinterpret_cast<bf162*>(&ol[o0 + 2]) = b;
}

// out = LayerNorm(X + Y) * g + b ; optional hi/lo split output
__global__ __launch_bounds__(256)
void add_ln_k(const float* __restrict__ X, const float* __restrict__ Y,
              const float* __restrict__ g, const float* __restrict__ b,
              float* __restrict__ out, bf16* __restrict__ oh, bf16* __restrict__ ol)
{
    __shared__ float s1[8], s2[8];
    size_t row = (size_t)blockIdx.x * Dn;
    int tid = threadIdx.x;
    float4 x = *reinterpret_cast<const float4*>(X + row + tid * 4);
    float4 y = *reinterpret_cast<const float4*>(Y + row + tid * 4);
    float4 v; v.x = x.x + y.x; v.y = x.y + y.y; v.z = x.z + y.z; v.w = x.w + y.w;
    float sum = v.x + v.y + v.z + v.w;
    float sq  = v.x*v.x + v.y*v.y + v.z*v.z + v.w*v.w;
#pragma unroll
    for (int o = 16; o; o >>= 1) {
        sum += __shfl_xor_sync(0xffffffffu, sum, o);
        sq  += __shfl_xor_sync(0xffffffffu, sq,  o);
    }
    if ((tid & 31) == 0) { s1[tid >> 5] = sum; s2[tid >> 5] = sq; }
    __syncthreads();
    if (tid == 0) {
        float a = 0.f, c = 0.f;
#pragma unroll
        for (int i = 0; i < 8; i++) { a += s1[i]; c += s2[i]; }
        s1[0] = a; s2[0] = c;
    }
    __syncthreads();
    float mean = s1[0] * (1.f / Dn);
    float var  = s2[0] * (1.f / Dn) - mean * mean;
    float inv  = rsqrtf(var + 1e-5f);
    float4 gg = *reinterpret_cast<const float4*>(g + tid * 4);
    float4 bb = *reinterpret_cast<const float4*>(b + tid * 4);
    float4 o;
    o.x = (v.x - mean) * inv * gg.x + bb.x;
    o.y = (v.y - mean) * inv * gg.y + bb.y;
    o.z = (v.z - mean) * inv * gg.z + bb.z;
    o.w = (v.w - mean) * inv * gg.w + bb.w;
    if (out) *reinterpret_cast<float4*>(out + row + tid * 4) = o;
    if (oh) {
        bf16 h0, l0, h1, l1, h2, l2, h3, l3;
        split2(o.x, h0, l0); split2(o.y, h1, l1);
        split2(o.z, h2, l2); split2(o.w, h3, l3);
        bf162 a2, b2;
        size_t o0 = row + tid * 4;
        a2.x = h0; a2.y = h1; b2.x = h2; b2.y = h3;
        *reinterpret_cast<bf162*>(&oh[o0]) = a2;
        *reinterpret_cast<bf162*>(&oh[o0 + 2]) = b2;
        a2.x = l0; a2.y = l1; b2.x = l2; b2.y = l3;
        *reinterpret_cast<bf162*>(&ol[o0]) = a2;
        *reinterpret_cast<bf162*>(&ol[o0 + 2]) = b2;
    }
}

// ---------------- host side ----------------
extern "C" void kernel_launch(void* const* d_in, const int* in_sizes, int n_in,
                              void* d_out, int out_size)
{
    const float* src = (const float*)d_in[0];
    const float* aux = (const float*)d_in[1];
    const float* Wu  = (const float*)d_in[2];
    const float* bu  = (const float*)d_in[3];
    const float* Wv  = (const float*)d_in[4];
    const float* bv  = (const float*)d_in[5];
    const float* Wo  = (const float*)d_in[6];
    const float* bo  = (const float*)d_in[7];
    const float* W1  = (const float*)d_in[8];
    const float* b1  = (const float*)d_in[9];
    const float* W2  = (const float*)d_in[10];
    const float* b2  = (const float*)d_in[11];
    const float* g1  = (const float*)d_in[12];
    const float* be1 = (const float*)d_in[13];
    const float* g2  = (const float*)d_in[14];
    const float* be2 = (const float*)d_in[15];
    const int* src_mask = (const int*)d_in[16];
    const int* aux_mask = (const int*)d_in[17];
    float* out = (float*)d_out;

    unsigned char* pool;
    cudaGetSymbolAddress((void**)&pool, g_pool);
    float* comb = (float*)(pool + O_COMB);
    float* proj = (float*)(pool + O_PROJ);
    float* o1   = (float*)(pool + O_O1);
    bf16 *srch = (bf16*)(pool + O_SRCH), *srcl = (bf16*)(pool + O_SRCL);
    bf16 *auxh = (bf16*)(pool + O_AUXH), *auxl = (bf16*)(pool + O_AUXL);
    bf16 *WuTh = (bf16*)(pool + O_WUTH), *WuTl = (bf16*)(pool + O_WUTL);
    bf16 *WvTh = (bf16*)(pool + O_WVTH), *WvTl = (bf16*)(pool + O_WVTL);
    bf16 *WoTh = (bf16*)(pool + O_WOTH), *WoTl = (bf16*)(pool + O_WOTL);
    bf16 *W1Th = (bf16*)(pool + O_W1TH), *W1Tl = (bf16*)(pool + O_W1TL);
    bf16 *W2Th = (bf16*)(pool + O_W2TH), *W2Tl = (bf16*)(pool + O_W2TL);
    bf16 *quh = (bf16*)(pool + O_QUH), *qul = (bf16*)(pool + O_QUL);
    bf16 *qvh = (bf16*)(pool + O_QVH), *qvl = (bf16*)(pool + O_QVL);
    bf16 *s1h = (bf16*)(pool + O_S1H), *s1l = (bf16*)(pool + O_S1L);
    bf16 *s2h = (bf16*)(pool + O_S2H), *s2l = (bf16*)(pool + O_S2L);
    bf16 *s1th = (bf16*)(pool + O_S1TH), *s1tl = (bf16*)(pool + O_S1TL);
    bf16 *s2th = (bf16*)(pool + O_S2TH), *s2tl = (bf16*)(pool + O_S2TL);
    bf16 *atth = (bf16*)(pool + O_ATTH), *attl = (bf16*)(pool + O_ATTL);
    bf16 *vtuh = (bf16*)(pool + O_VTUH), *vtul = (bf16*)(pool + O_VTUL);
    bf16 *vtvh = (bf16*)(pool + O_VTVH), *vtvl = (bf16*)(pool + O_VTVL);
    bf16 *hdh = (bf16*)(pool + O_HDH), *hdl = (bf16*)(pool + O_HDL);
    bf16 *o1h = (bf16*)(pool + O_O1H), *o1l = (bf16*)(pool + O_O1L);
    bf16 *ffhh = (bf16*)(pool + O_FFHH), *ffhl = (bf16*)(pool + O_FFHL);

    cudaFuncSetAttribute(hgemm_k<128>, cudaFuncAttributeMaxDynamicSharedMemorySize, 2 * (2 * 16384 + 2 * 128 * 128) + 1024);
    cudaFuncSetAttribute(hgemm_k<64>,  cudaFuncAttributeMaxDynamicSharedMemorySize, 2 * (2 * 16384 + 2 * 64 * 128) + 1024);
    cudaFuncSetAttribute(comb_mma_k,   cudaFuncAttributeMaxDynamicSharedMemorySize, SMEM_COMB);

    const int SM128 = 2 * (2 * 16384 + 2 * 128 * 128) + 1024;   // 132096
    const int SM64  = 2 * (2 * 16384 + 2 * 64 * 128) + 1024;    // 99328

    const long long sQKVr = (long long)Tn * 3 * An;
    const long long sT2   = (long long)Tn * Tn;
    const long long sHT2  = (long long)Hn * Tn * Tn;

    // ---- input & weight splits
    split_k<<<(int)((N_BTD / 4 + 255) / 256), 256>>>((const float4*)src, (bf162*)srch, (bf162*)srcl, (int)(N_BTD / 4));
    split_k<<<(int)((N_BTD / 4 + 255) / 256), 256>>>((const float4*)aux, (bf162*)auxh, (bf162*)auxl, (int)(N_BTD / 4));
    wsplitT_k<<<dim3(3 * An / 32, Dn / 32), 256>>>(Wu, WuTh, WuTl, 3 * An, Dn);
    wsplitT_k<<<dim3(3 * An / 32, Dn / 32), 256>>>(Wv, WvTh, WvTl, 3 * An, Dn);
    wsplitT_k<<<dim3(Dn / 32, An / 32), 256>>>(Wo, WoTh, WoTl, Dn, An);
    wsplitT_k<<<dim3(Fn / 32, Dn / 32), 256>>>(W1, W1Th, W1Tl, Fn, Dn);
    wsplitT_k<<<dim3(Dn / 32, Fn / 32), 256>>>(W2, W2Th, W2Tl, Dn, Fn);

    // ---- QKV projections (hi/lo outputs only)
    hgemm_k<128><<<dim3(24, 16, 1), 256, SM128>>>(
        srch, srcl, WuTh, WuTl, nullptr, quh, qul,
        Dn, Dn, Dn, 3 * An, 0, 0, 0, 0, 0, 0, 1, bu, nullptr, 0, 1.f, 0);
    hgemm_k<128><<<dim3(24, 16, 1), 256, SM128>>>(
        auxh, auxl, WvTh, WvTl, nullptr, qvh, qvl,
        Dn, Dn, Dn, 3 * An, 0, 0, 0, 0, 0, 0, 1, bv, nullptr, 0, 1.f, 0);

    // ---- sim1 = (Qu/8)@Kv^T (mask: aux_mask) ; sim2 = (Qv/8)@Ku^T (mask: src_mask)
    hgemm_k<128><<<dim3(8, 8, ZHn), 256, SM128>>>(
        quh, qul, qvh + An, qvl + An, nullptr, s1h, s1l,
        HDn, 3 * An, 3 * An, Tn,
        sQKVr, HDn, sQKVr, HDn, sHT2, sT2, Hn, nullptr, aux_mask, Tn, 0.125f, 0);
    hgemm_k<128><<<dim3(8, 8, ZHn), 256, SM128>>>(
        qvh, qvl, quh + An, qul + An, nullptr, s2h, s2l,
        HDn, 3 * An, 3 * An, Tn,
        sQKVr, HDn, sQKVr, HDn, sHT2, sT2, Hn, nullptr, src_mask, Tn, 0.125f, 0);

    // ---- transposed sim splits + V^T splits
    btran_k<<<dim3(32, 32, ZHn), 256>>>(s1h, s1l, s1th, s1tl, Tn, Tn, sT2, 0, sT2, 1);
    btran_k<<<dim3(32, 32, ZHn), 256>>>(s2h, s2l, s2th, s2tl, Tn, Tn, sT2, 0, sT2, 1);
    btran_k<<<dim3(2, 32, ZHn), 256>>>(quh + 2 * An, qul + 2 * An, vtuh, vtul,
                                       3 * An, Tn, sQKVr, HDn, (long long)HDn * Tn, Hn);
    btran_k<<<dim3(2, 32, ZHn), 256>>>(qvh + 2 * An, qvl + 2 * An, vtvh, vtvl,
                                       3 * An, Tn, sQKVr, HDn, (long long)HDn * Tn, Hn);

    dim3 cgrid(8, 8, ZHn);

    // ================= stream U =================
    comb_mma_k<<<cgrid, 256, SMEM_COMB>>>(s1h, s1l, s2th, s2tl, comb);
    softmax_bf_k<<<ZHn * Tn, 256>>>(comb, atth, attl);
    hgemm_k<64><<<dim3(1, 8, ZHn), 256, SM64>>>(
        atth, attl, vtuh, vtul, nullptr, hdh, hdl,
        Tn, Tn, Tn, An,
        (long long)Hn * sT2, sT2, (long long)Hn * HDn * Tn, (long long)HDn * Tn,
        (long long)Tn * An, HDn, Hn, nullptr, nullptr, 0, 1.f, 0);
    hgemm_k<128><<<dim3(8, 16, 1), 256, SM128>>>(
        hdh, hdl, WoTh, WoTl, proj, nullptr, nullptr,
        An, An, An, Dn, 0, 0, 0, 0, 0, 0, 1, bo, nullptr, 0, 1.f, 0);
    add_ln_k<<<BTn, 256>>>(src, proj, g1, be1, o1, o1h, o1l);
    hgemm_k<128><<<dim3(32, 16, 1), 256, SM128>>>(
        o1h, o1l, W1Th, W1Tl, nullptr, ffhh, ffhl,
        Dn, Dn, Dn, Fn, 0, 0, 0, 0, 0, 0, 1, b1, nullptr, 0, 1.f, 1);
    hgemm_k<128><<<dim3(8, 16, 1), 256, SM128>>>(
        ffhh, ffhl, W2Th, W2Tl, proj, nullptr, nullptr,
        Fn, Fn, Fn, Dn, 0, 0, 0, 0, 0, 0, 1, b2, nullptr, 0, 1.f, 0);
    add_ln_k<<<BTn, 256>>>(o1, proj, g2, be2, out, nullptr, nullptr);

    // ================= stream V =================
    comb_mma_k<<<cgrid, 256, SMEM_COMB>>>(s2h, s2l, s1th, s1tl, comb);
    softmax_bf_k<<<ZHn * Tn, 256>>>(comb, atth, attl);
    hgemm_k<64><<<dim3(1, 8, ZHn), 256, SM64>>>(
        atth, attl, vtvh, vtvl, nullptr, hdh, hdl,
        Tn, Tn, Tn, An,
        (long long)Hn * sT2, sT2, (long long)Hn * HDn * Tn, (long long)HDn * Tn,
        (long long)Tn * An, HDn, Hn, nullptr, nullptr, 0, 1.f, 0);
    hgemm_k<128><<<dim3(8, 16, 1), 256, SM128>>>(
        hdh, hdl, WoTh, WoTl, proj, nullptr, nullptr,
        An, An, An, Dn, 0, 0, 0, 0, 0, 0, 1, bo, nullptr, 0, 1.f, 0);
    add_ln_k<<<BTn, 256>>>(aux, proj, g1, be1, o1, o1h, o1l);
    hgemm_k<128><<<dim3(32, 16, 1), 256, SM128>>>(
        o1h, o1l, W1Th, W1Tl, nullptr, ffhh, ffhl,
        Dn, Dn, Dn, Fn, 0, 0, 0, 0, 0, 0, 1, b1, nullptr, 0, 1.f, 1);
    hgemm_k<128><<<dim3(8, 16, 1), 256, SM128>>>(
        ffhh, ffhl, W2Th, W2Tl, proj, nullptr, nullptr,
        Fn, Fn, Fn, Dn, 0, 0, 0, 0, 0, 0, 1, b2, nullptr, 0, 1.f, 0);
    add_ln_k<<<BTn, 256>>>(o1, proj, g2, be2, out + (size_t)BTn * Dn, nullptr, nullptr);
}

// round 11
// speedup vs baseline: 3.1178x; 1.1340x over previous
#include <cuda_runtime.h>
#include <cuda_bf16.h>
#include <math.h>
#include <stdint.h>

typedef __nv_bfloat16 bf16;
typedef __nv_bfloat162 bf162;

// Problem constants
#define Tn   1024
#define Dn   1024
#define Hn   16
#define HDn  64
#define An   1024
#define Fn   4096
#define Bn   2
#define BTn  (Bn*Tn)       // 2048
#define ZHn  (Bn*Hn)       // 32

// ---------------- scratch pool (allocation-free) ----------------
#define N_T2   ((size_t)ZHn*Tn*Tn)
#define N_BTD  ((size_t)BTn*Dn)
#define N_QKV  ((size_t)BTn*3*An)
#define N_W3   ((size_t)3*An*Dn)
#define N_WF   ((size_t)Fn*Dn)
#define N_BTF  ((size_t)BTn*Fn)
#define N_VT   ((size_t)ZHn*HDn*Tn)

static constexpr size_t O_COMB = 0;
static constexpr size_t O_PROJ = O_COMB + N_T2*4;
static constexpr size_t O_O1   = O_PROJ + N_BTD*4;
static constexpr size_t O_SRCH = O_O1   + N_BTD*4;
static constexpr size_t O_SRCL = O_SRCH + N_BTD*2;
static constexpr size_t O_AUXH = O_SRCL + N_BTD*2;
static constexpr size_t O_AUXL = O_AUXH + N_BTD*2;
static constexpr size_t O_WUTH = O_AUXL + N_BTD*2;
static constexpr size_t O_WUTL = O_WUTH + N_W3*2;
static constexpr size_t O_WVTH = O_WUTL + N_W3*2;
static constexpr size_t O_WVTL = O_WVTH + N_W3*2;
static constexpr size_t O_WOTH = O_WVTL + N_W3*2;
static constexpr size_t O_WOTL = O_WOTH + (size_t)An*Dn*2;
static constexpr size_t O_W1TH = O_WOTL + (size_t)An*Dn*2;
static constexpr size_t O_W1TL = O_W1TH + N_WF*2;
static constexpr size_t O_W2TH = O_W1TL + N_WF*2;
static constexpr size_t O_W2TL = O_W2TH + N_WF*2;
static constexpr size_t O_QUH  = O_W2TL + N_WF*2;
static constexpr size_t O_QUL  = O_QUH  + N_QKV*2;
static constexpr size_t O_QVH  = O_QUL  + N_QKV*2;
static constexpr size_t O_QVL  = O_QVH  + N_QKV*2;
static constexpr size_t O_S1H  = O_QVL  + N_QKV*2;
static constexpr size_t O_S1L  = O_S1H  + N_T2*2;
static constexpr size_t O_S2H  = O_S1L  + N_T2*2;
static constexpr size_t O_S2L  = O_S2H  + N_T2*2;
static constexpr size_t O_S1TPH = O_S2L  + N_T2*2;   // sim1^T packed by src (B for comb V)
static constexpr size_t O_S1TPL = O_S1TPH + N_T2*2;
static constexpr size_t O_S2TPH = O_S1TPL + N_T2*2;  // sim2^T packed by aux (B for comb U)
static constexpr size_t O_S2TPL = O_S2TPH + N_T2*2;
static constexpr size_t O_ATTH = O_S2TPL + N_T2*2;
static constexpr size_t O_ATTL = O_ATTH + N_T2*2;
static constexpr size_t O_VTUH = O_ATTL + N_T2*2;
static constexpr size_t O_VTUL = O_VTUH + N_VT*2;
static constexpr size_t O_VTVH = O_VTUL + N_VT*2;
static constexpr size_t O_VTVL = O_VTVH + N_VT*2;
static constexpr size_t O_HDH  = O_VTVL + N_VT*2;
static constexpr size_t O_HDL  = O_HDH  + (size_t)BTn*An*2;
static constexpr size_t O_O1H  = O_HDL  + (size_t)BTn*An*2;
static constexpr size_t O_O1L  = O_O1H  + N_BTD*2;
static constexpr size_t O_FFHH = O_O1L  + N_BTD*2;
static constexpr size_t O_FFHL = O_FFHH + N_BTF*2;
static constexpr size_t O_S1PH = O_FFHL + N_BTF*2;   // sim1 cols packed by aux (A for comb U)
static constexpr size_t O_S1PL = O_S1PH + N_T2*2;
static constexpr size_t O_S2PH = O_S1PL + N_T2*2;    // sim2 cols packed by src (A for comb V)
static constexpr size_t O_S2PL = O_S2PH + N_T2*2;
static constexpr size_t O_IDXU = O_S2PL + N_T2*2;    // int[2][1024]
static constexpr size_t O_IDXV = O_IDXU + (size_t)2*Tn*4;
static constexpr size_t O_KIU  = O_IDXV + (size_t)2*Tn*4;  // int[4]: {kpad0,cnt0,kpad1,cnt1}
static constexpr size_t O_KIV  = O_KIU  + 64;
static constexpr size_t POOL_BYTES = O_KIV + 64;

__device__ __align__(1024) unsigned char g_pool[POOL_BYTES];

// ===================== portable PTX helpers (sm_80+) =====================
__device__ __forceinline__ uint32_t smem_u32(const void* p) {
    uint32_t a;
    asm("{ .reg .u64 t; cvta.to.shared.u64 t, %1; cvt.u32.u64 %0, t; }" : "=r"(a) : "l"(p));
    return a;
}
#define SW128(off) ((off) ^ (((off) >> 3) & 0x70))

__device__ __forceinline__ void cp_async16(uint32_t saddr, const void* gptr) {
    asm volatile("cp.async.cg.shared.global [%0], [%1], 16;" :: "r"(saddr), "l"(gptr) : "memory");
}
__device__ __forceinline__ void cp_commit() {
    asm volatile("cp.async.commit_group;" ::: "memory");
}
template<int N>
__device__ __forceinline__ void cp_wait() {
    asm volatile("cp.async.wait_group %0;" :: "n"(N) : "memory");
}
__device__ __forceinline__ void ldsm4(uint32_t* r, uint32_t addr) {
    asm volatile("ldmatrix.sync.aligned.m8n8.x4.shared.b16 {%0,%1,%2,%3}, [%4];"
                 : "=r"(r[0]), "=r"(r[1]), "=r"(r[2]), "=r"(r[3]) : "r"(addr));
}
__device__ __forceinline__ void mma_bf16(float* c, const uint32_t* a, const uint32_t* b) {
    asm volatile("mma.sync.aligned.m16n8k16.row.col.f32.bf16.bf16.f32 "
                 "{%0,%1,%2,%3}, {%4,%5,%6,%7}, {%8,%9}, {%0,%1,%2,%3};"
                 : "+f"(c[0]), "+f"(c[1]), "+f"(c[2]), "+f"(c[3])
                 : "r"(a[0]), "r"(a[1]), "r"(a[2]), "r"(a[3]), "r"(b[0]), "r"(b[1]));
}
__device__ __forceinline__ void split2(float v, bf16& h, bf16& l) {
    h = __float2bfloat16_rn(v);
    l = __float2bfloat16_rn(v - __bfloat162float(h));
}

// ===================== generic bf16x3 HMMA GEMM =====================
template<int BNT>
__global__ __launch_bounds__(256, 1)
void hgemm_k(const bf16* __restrict__ Ah, const bf16* __restrict__ Al,
             const bf16* __restrict__ Bh, const bf16* __restrict__ Bl,
             float* __restrict__ C, bf16* __restrict__ Oh, bf16* __restrict__ Ol,
             int K, int lda, int ldb, int ldc,
             long long sA1, long long sA2, long long sB1, long long sB2,
             long long sC1, long long sC2, int Hdiv,
             const float* __restrict__ bias, const int* __restrict__ mask,
             int maskStride, float alpha, int relu)
{
    constexpr int ABYTES = 16384;
    constexpr int BBYTES = BNT * 128;
    constexpr int SS = 2 * ABYTES + 2 * BBYTES;
    extern __shared__ char smraw[];
    uint32_t raw = smem_u32(smraw);
    uint32_t base = (raw + 1023u) & ~1023u;

    int tid = threadIdx.x, wid = tid >> 5, lane = tid & 31;
    int z = blockIdx.z, zb = z / Hdiv, zh = z % Hdiv;
    int m0 = blockIdx.y * 128, n0 = blockIdx.x * BNT;
    Ah += zb * sA1 + zh * sA2 + (size_t)m0 * lda;
    Al += zb * sA1 + zh * sA2 + (size_t)m0 * lda;
    Bh += zb * sB1 + zh * sB2 + (size_t)n0 * ldb;
    Bl += zb * sB1 + zh * sB2 + (size_t)n0 * ldb;
    long long coff = zb * sC1 + zh * sC2 + (long long)m0 * ldc + n0;
    const int* pmask = mask ? mask + (size_t)zb * maskStride + n0 : nullptr;
    const float* pbias = bias ? bias + n0 : nullptr;

    auto load_stage = [&](int s, int kc) {
        uint32_t sb = base + (uint32_t)s * SS;
#pragma unroll
        for (int i = 0; i < 4; i++) {
            int q = tid + i * 256;
            int r = q >> 3, cb = q & 7;
            uint32_t sw = SW128((uint32_t)(r * 128 + cb * 16));
            size_t go = (size_t)r * lda + kc * 64 + cb * 8;
            cp_async16(sb + sw, Ah + go);
            cp_async16(sb + ABYTES + sw, Al + go);
        }
#pragma unroll
        for (int i = 0; i < BNT / 32; i++) {
            int q = tid + i * 256;
            int r = q >> 3, cb = q & 7;
            uint32_t sw = SW128((uint32_t)(r * 128 + cb * 16));
            size_t go = (size_t)r * ldb + kc * 64 + cb * 8;
            cp_async16(sb + 2 * ABYTES + sw, Bh + go);
            cp_async16(sb + 2 * ABYTES + BBYTES + sw, Bl + go);
        }
        cp_commit();
    };

    int wm = (wid >> 1) * 32;
    int wn = (wid & 1) * (BNT / 2);

    float acc[2][BNT / 16][4];
#pragma unroll
    for (int a = 0; a < 2; a++)
#pragma unroll
        for (int b = 0; b < BNT / 16; b++)
#pragma unroll
            for (int c = 0; c < 4; c++) acc[a][b][c] = 0.f;

    int a_row = wm + (lane & 15);
    int a_cb  = (lane >> 4) * 16;
    int b_row = wn + (lane & 7) + ((lane >> 4) << 3);
    int b_cb  = ((lane >> 3) & 1) * 16;

    load_stage(0, 0);
    int NCH = K / 64;

    for (int c = 0; c < NCH; c++) {
        if (c + 1 < NCH) { load_stage((c + 1) & 1, c + 1); cp_wait<1>(); }
        else             { cp_wait<0>(); }
        __syncthreads();

        uint32_t sb = base + (uint32_t)(c & 1) * SS;
        uint32_t sAh = sb, sAl = sb + ABYTES;
        uint32_t sBh = sb + 2 * ABYTES, sBl = sb + 2 * ABYTES + BBYTES;

#pragma unroll
        for (int ks = 0; ks < 4; ks++) {
            uint32_t ah[2][4], al[2][4];
            int acol = ks * 32 + a_cb;
#pragma unroll
            for (int mi = 0; mi < 2; mi++) {
                int sw = SW128((a_row + mi * 16) * 128 + acol);
                ldsm4(ah[mi], sAh + sw);
                ldsm4(al[mi], sAl + sw);
            }
            int bcol = ks * 32 + b_cb;
#pragma unroll
            for (int np = 0; np < BNT / 32; np++) {
                int sw = SW128((b_row + np * 16) * 128 + bcol);
                uint32_t bh[4], bl[4];
                ldsm4(bh, sBh + sw);
#pragma unroll
                for (int mi = 0; mi < 2; mi++) {
                    mma_bf16(acc[mi][np * 2 + 0], ah[mi], bh + 0);
                    mma_bf16(acc[mi][np * 2 + 1], ah[mi], bh + 2);
                    mma_bf16(acc[mi][np * 2 + 0], al[mi], bh + 0);
                    mma_bf16(acc[mi][np * 2 + 1], al[mi], bh + 2);
                }
                ldsm4(bl, sBl + sw);
#pragma unroll
                for (int mi = 0; mi < 2; mi++) {
                    mma_bf16(acc[mi][np * 2 + 0], ah[mi], bl + 0);
                    mma_bf16(acc[mi][np * 2 + 1], ah[mi], bl + 2);
                }
            }
        }
        __syncthreads();
    }

    int g = lane >> 2, tig = lane & 3;
#pragma unroll
    for (int mi = 0; mi < 2; mi++) {
#pragma unroll
        for (int ni = 0; ni < BNT / 16; ni++) {
            int mrow = wm + mi * 16 + g;
            int ncol = wn + ni * 8 + tig * 2;
            float v0 = acc[mi][ni][0] * alpha;
            float v1 = acc[mi][ni][1] * alpha;
            float v2 = acc[mi][ni][2] * alpha;
            float v3 = acc[mi][ni][3] * alpha;
            if (pbias) {
                float b0 = pbias[ncol], b1 = pbias[ncol + 1];
                v0 += b0; v1 += b1; v2 += b0; v3 += b1;
            }
            if (relu) {
                v0 = fmaxf(v0, 0.f); v1 = fmaxf(v1, 0.f);
                v2 = fmaxf(v2, 0.f); v3 = fmaxf(v3, 0.f);
            }
            if (pmask) {
                if (pmask[ncol] == 0)     { v0 = 1e-32f; v2 = 1e-32f; }
                if (pmask[ncol + 1] == 0) { v1 = 1e-32f; v3 = 1e-32f; }
            }
            long long o0 = coff + (long long)mrow * ldc + ncol;
            long long o1 = o0 + (long long)8 * ldc;
            if (C) {
                float2 f0; f0.x = v0; f0.y = v1;
                float2 f1; f1.x = v2; f1.y = v3;
                *reinterpret_cast<float2*>(&C[o0]) = f0;
                *reinterpret_cast<float2*>(&C[o1]) = f1;
            }
            if (Oh) {
                bf16 h0, l0, h1, l1, h2, l2, h3, l3;
                split2(v0, h0, l0); split2(v1, h1, l1);
                split2(v2, h2, l2); split2(v3, h3, l3);
                bf162 hv0; hv0.x = h0; hv0.y = h1;
                bf162 hv1; hv1.x = h2; hv1.y = h3;
                bf162 lv0; lv0.x = l0; lv0.y = l1;
                bf162 lv1; lv1.x = l2; lv1.y = l3;
                *reinterpret_cast<bf162*>(&Oh[o0]) = hv0;
                *reinterpret_cast<bf162*>(&Oh[o1]) = hv1;
                *reinterpret_cast<bf162*>(&Ol[o0]) = lv0;
                *reinterpret_cast<bf162*>(&Ol[o1]) = lv1;
            }
        }
    }
}

// ===================== comb MMA kernel (dynamic masked-K) =====================
#define MAT_BYTES 16384
#define STAGE_BYTES (4*MAT_BYTES)
#define SMEM_COMB (2*STAGE_BYTES + 1024)

__global__ __launch_bounds__(256, 1)
void comb_mma_k(const bf16* __restrict__ Ah, const bf16* __restrict__ Al,
                const bf16* __restrict__ Bh, const bf16* __restrict__ Bl,
                float* __restrict__ C, const int* __restrict__ kinfo)
{
    extern __shared__ char smraw[];
    uint32_t raw  = smem_u32(smraw);
    uint32_t base = (raw + 1023u) & ~1023u;

    int tid = threadIdx.x, wid = tid >> 5, lane = tid & 31;
    int z = blockIdx.z, m0 = blockIdx.y * 128, n0 = blockIdx.x * 128;
    int NCH = kinfo[(z / Hn) * 2] >> 6;   // Kpad/64, data-dependent
    size_t zoff = (size_t)z * Tn * Tn;
    const bf16* pAh = Ah + zoff + (size_t)m0 * Tn;
    const bf16* pAl = Al + zoff + (size_t)m0 * Tn;
    const bf16* pBh = Bh + zoff + (size_t)n0 * Tn;
    const bf16* pBl = Bl + zoff + (size_t)n0 * Tn;
    float* pC = C + zoff + (size_t)m0 * Tn + n0;

    int lr[4], lsw[4];
#pragma unroll
    for (int i = 0; i < 4; i++) {
        int q = tid + i * 256;
        lr[i]  = q >> 3;
        int c  = q & 7;
        lsw[i] = SW128(lr[i] * 128 + c * 16);
    }

    auto load_stage = [&](int s, int kc) {
        uint32_t sb = base + (uint32_t)s * STAGE_BYTES;
#pragma unroll
        for (int i = 0; i < 4; i++) {
            size_t go = (size_t)lr[i] * Tn + kc * 64 + ((tid + i * 256) & 7) * 8;
            cp_async16(sb + 0 * MAT_BYTES + lsw[i], pAh + go);
            cp_async16(sb + 1 * MAT_BYTES + lsw[i], pAl + go);
            cp_async16(sb + 2 * MAT_BYTES + lsw[i], pBh + go);
            cp_async16(sb + 3 * MAT_BYTES + lsw[i], pBl + go);
        }
        cp_commit();
    };

    int wm = (wid >> 1) * 32;
    int wn = (wid & 1) * 64;

    float acc[2][8][4];
#pragma unroll
    for (int a = 0; a < 2; a++)
#pragma unroll
        for (int b = 0; b < 8; b++)
#pragma unroll
            for (int c = 0; c < 4; c++) acc[a][b][c] = 0.f;

    int a_row = wm + (lane & 15);
    int a_cb  = (lane >> 4) * 16;
    int b_row = wn + (lane & 7) + ((lane >> 4) << 3);
    int b_cb  = ((lane >> 3) & 1) * 16;

    if (NCH > 0) {
        load_stage(0, 0);
        for (int c = 0; c < NCH; c++) {
            if (c + 1 < NCH) { load_stage((c + 1) & 1, c + 1); cp_wait<1>(); }
            else             { cp_wait<0>(); }
            __syncthreads();

            uint32_t sb = base + (uint32_t)(c & 1) * STAGE_BYTES;
            uint32_t sAh = sb, sAl = sb + MAT_BYTES, sBh = sb + 2 * MAT_BYTES, sBl = sb + 3 * MAT_BYTES;

#pragma unroll
            for (int ks = 0; ks < 4; ks++) {
                uint32_t ah[2][4], al[2][4];
                int acol = ks * 32 + a_cb;
#pragma unroll
                for (int mi = 0; mi < 2; mi++) {
                    int sw = SW128((a_row + mi * 16) * 128 + acol);
                    ldsm4(ah[mi], sAh + sw);
                    ldsm4(al[mi], sAl + sw);
                }
                int bcol = ks * 32 + b_cb;
#pragma unroll
                for (int np = 0; np < 4; np++) {
                    int sw = SW128((b_row + np * 16) * 128 + bcol);
                    uint32_t bh[4], bl[4];
                    ldsm4(bh, sBh + sw);
#pragma unroll
                    for (int mi = 0; mi < 2; mi++) {
                        mma_bf16(acc[mi][np * 2 + 0], ah[mi], bh + 0);
                        mma_bf16(acc[mi][np * 2 + 1], ah[mi], bh + 2);
                        mma_bf16(acc[mi][np * 2 + 0], al[mi], bh + 0);
                        mma_bf16(acc[mi][np * 2 + 1], al[mi], bh + 2);
                    }
                    ldsm4(bl, sBl + sw);
#pragma unroll
                    for (int mi = 0; mi < 2; mi++) {
                        mma_bf16(acc[mi][np * 2 + 0], ah[mi], bl + 0);
                        mma_bf16(acc[mi][np * 2 + 1], ah[mi], bl + 2);
                    }
                }
            }
            __syncthreads();
        }
    }

    int g = lane >> 2, tig = lane & 3;
#pragma unroll
    for (int mi = 0; mi < 2; mi++) {
#pragma unroll
        for (int ni = 0; ni < 8; ni++) {
            int mrow = wm + mi * 16 + g;
            int ncol = wn + ni * 8 + tig * 2;
            float2 v0; v0.x = acc[mi][ni][0]; v0.y = acc[mi][ni][1];
            float2 v1; v1.x = acc[mi][ni][2]; v1.y = acc[mi][ni][3];
            *reinterpret_cast<float2*>(&pC[(size_t)mrow * Tn + ncol]) = v0;
            *reinterpret_cast<float2*>(&pC[(size_t)(mrow + 8) * Tn + ncol]) = v1;
        }
    }
}

// ===================== mask index scan =====================
__global__ __launch_bounds__(1024)
void maskidx_k(const int* __restrict__ mask, int* __restrict__ idx, int* __restrict__ kinfo)
{
    __shared__ int arr[1024];
    int zb = blockIdx.x, t = threadIdx.x;
    int m = (mask[zb * Tn + t] != 0) ? 1 : 0;
    arr[t] = m;
    __syncthreads();
    for (int off = 1; off < 1024; off <<= 1) {
        int v = (t >= off) ? arr[t - off] : 0;
        __syncthreads();
        arr[t] += v;
        __syncthreads();
    }
    if (m) idx[zb * Tn + arr[t] - 1] = t;
    if (t == 1023) {
        int cnt = arr[1023];
        kinfo[zb * 2 + 0] = (cnt + 63) / 64 * 64;
        kinfo[zb * 2 + 1] = cnt;
    }
}

// ===================== pack kernels =====================
// column gather: out[z][i][kk] = in[z][i][idx[zb][kk]]  (kk<cnt; zero to kpad)
__global__ __launch_bounds__(256)
void packg_k(const bf16* __restrict__ inH, const bf16* __restrict__ inL,
             bf16* __restrict__ outH, bf16* __restrict__ outL,
             const int* __restrict__ idx, const int* __restrict__ kinfo)
{
    int z = blockIdx.z, zb = z / Hn;
    int kpad = kinfo[zb * 2], cnt = kinfo[zb * 2 + 1];
    int kk = blockIdx.x * 256 + threadIdx.x;
    if (kk >= kpad) return;
    int i = blockIdx.y;
    size_t ro = (size_t)z * Tn * Tn + (size_t)i * Tn;
    bf16 h = __float2bfloat16_rn(0.f), l = h;
    if (kk < cnt) {
        int k = idx[zb * Tn + kk];
        h = inH[ro + k]; l = inL[ro + k];
    }
    outH[ro + kk] = h;
    outL[ro + kk] = l;
}

// gather-transpose: out[z][j][kk] = in[z][idx[zb][kk]][j]  (kk<cnt; zero to kpad)
__global__ __launch_bounds__(256)
void packt_k(const bf16* __restrict__ inH, const bf16* __restrict__ inL,
             bf16* __restrict__ outH, bf16* __restrict__ outL,
             const int* __restrict__ idx, const int* __restrict__ kinfo)
{
    __shared__ bf16 th[32][34], tl[32][34];
    int z = blockIdx.z, zb = z / Hn;
    int kpad = kinfo[zb * 2], cnt = kinfo[zb * 2 + 1];
    int k0 = blockIdx.x * 32;
    if (k0 >= kpad) return;
    int j0 = blockIdx.y * 32;
    int tx = threadIdx.x & 31, ty = threadIdx.x >> 5;  // 32 x 8
    size_t zo = (size_t)z * Tn * Tn;
    bf16 zero = __float2bfloat16_rn(0.f);
#pragma unroll
    for (int i = 0; i < 4; i++) {
        int kr = k0 + ty + i * 8;
        bf16 h = zero, l = zero;
        if (kr < cnt) {
            int srck = idx[zb * Tn + kr];
            size_t o = zo + (size_t)srck * Tn + j0 + tx;
            h = inH[o]; l = inL[o];
        }
        th[ty + i * 8][tx] = h;
        tl[ty + i * 8][tx] = l;
    }
    __syncthreads();
#pragma unroll
    for (int i = 0; i < 4; i++) {
        size_t o = zo + (size_t)(j0 + ty + i * 8) * Tn + k0 + tx;
        outH[o] = th[tx][ty + i * 8];
        outL[o] = tl[tx][ty + i * 8];
    }
}

// ===================== elementwise kernels =====================
__global__ __launch_bounds__(256)
void split_k(const float4* __restrict__ in, bf162* __restrict__ hi,
             bf162* __restrict__ lo, int n4)
{
    int i = blockIdx.x * 256 + threadIdx.x;
    if (i >= n4) return;
    float4 v = in[i];
    bf16 h0, l0, h1, l1, h2, l2, h3, l3;
    split2(v.x, h0, l0); split2(v.y, h1, l1);
    split2(v.z, h2, l2); split2(v.w, h3, l3);
    bf162 a, b;
    a.x = h0; a.y = h1; b.x = h2; b.y = h3;
    hi[2 * i] = a; hi[2 * i + 1] = b;
    a.x = l0; a.y = l1; b.x = l2; b.y = l3;
    lo[2 * i] = a; lo[2 * i + 1] = b;
}

__global__ __launch_bounds__(256)
void wsplitT_k(const float* __restrict__ in, bf16* __restrict__ oh,
               bf16* __restrict__ ol, int ldin, int ldout)
{
    __shared__ float t[32][33];
    int x0 = blockIdx.x * 32, y0 = blockIdx.y * 32;
    int tx = threadIdx.x & 31, ty = threadIdx.x >> 5;
#pragma unroll
    for (int i = 0; i < 4; i++)
        t[ty + i * 8][tx] = in[(size_t)(y0 + ty + i * 8) * ldin + x0 + tx];
    __syncthreads();
#pragma unroll
    for (int i = 0; i < 4; i++) {
        float v = t[tx][ty + i * 8];
        bf16 h, l; split2(v, h, l);
        size_t o = (size_t)(x0 + ty + i * 8) * ldout + y0 + tx;
        oh[o] = h; ol[o] = l;
    }
}

__global__ __launch_bounds__(256)
void btran_k(const bf16* __restrict__ inH, const bf16* __restrict__ inL,
             bf16* __restrict__ outH, bf16* __restrict__ outL,
             int ldin, int ldout,
             long long sI1, long long sI2, long long sO, int Hdiv)
{
    __shared__ bf16 th[32][34], tl[32][34];
    int z = blockIdx.z, zb = z / Hdiv, zh = z % Hdiv;
    inH += zb * sI1 + zh * sI2; inL += zb * sI1 + zh * sI2;
    outH += (size_t)z * sO; outL += (size_t)z * sO;
    int x0 = blockIdx.x * 32, y0 = blockIdx.y * 32;
    int tx = threadIdx.x & 31, ty = threadIdx.x >> 5;
#pragma unroll
    for (int i = 0; i < 4; i++) {
        size_t o = (size_t)(y0 + ty + i * 8) * ldin + x0 + tx;
        th[ty + i * 8][tx] = inH[o];
        tl[ty + i * 8][tx] = inL[o];
    }
    __syncthreads();
#pragma unroll
    for (int i = 0; i < 4; i++) {
        size_t o = (size_t)(x0 + ty + i * 8) * ldout + y0 + tx;
        outH[o] = th[tx][ty + i * 8];
        outL[o] = tl[tx][ty + i * 8];
    }
}

__global__ __launch_bounds__(256)
void softmax_bf_k(const float* __restrict__ P, bf16* __restrict__ oh, bf16* __restrict__ ol)
{
    __shared__ float sdata[8];
    size_t row = blockIdx.x;
    const float4* p = reinterpret_cast<const float4*>(P + row * (size_t)Tn);
    int tid = threadIdx.x;
    float4 v = p[tid];
    float m = fmaxf(fmaxf(v.x, v.y), fmaxf(v.z, v.w));
#pragma unroll
    for (int o = 16; o; o >>= 1) m = fmaxf(m, __shfl_xor_sync(0xffffffffu, m, o));
    if ((tid & 31) == 0) sdata[tid >> 5] = m;
    __syncthreads();
    if (tid == 0) {
        float t = sdata[0];
#pragma unroll
        for (int i = 1; i < 8; i++) t = fmaxf(t, sdata[i]);
        sdata[0] = t;
    }
    __syncthreads();
    m = sdata[0];
    v.x = expf(v.x - m); v.y = expf(v.y - m);
    v.z = expf(v.z - m); v.w = expf(v.w - m);
    float s = v.x + v.y + v.z + v.w;
#pragma unroll
    for (int o = 16; o; o >>= 1) s += __shfl_xor_sync(0xffffffffu, s, o);
    __syncthreads();
    if ((tid & 31) == 0) sdata[tid >> 5] = s;
    __syncthreads();
    if (tid == 0) {
        float t = 0.f;
#pragma unroll
        for (int i = 0; i < 8; i++) t += sdata[i];
        sdata[0] = t;
    }
    __syncthreads();
    float inv = 1.f / sdata[0];
    v.x *= inv; v.y *= inv; v.z *= inv; v.w *= inv;
    bf16 h0, l0, h1, l1, h2, l2, h3, l3;
    split2(v.x, h0, l0); split2(v.y, h1, l1);
    split2(v.z, h2, l2); split2(v.w, h3, l3);
    bf162 a, b;
    size_t o0 = row * Tn + tid * 4;
    a.x = h0; a.y = h1; b.x = h2; b.y = h3;
    *reinterpret_cast<bf162*>(&oh[o0]) = a;
    *reinterpret_cast<bf162*>(&oh[o0 + 2]) = b;
    a.x = l0; a.y = l1; b.x = l2; b.y = l3;
    *reinterpret_cast<bf162*>(&ol[o0]) = a;
    *reinterpret_cast<bf162*>(&ol[o0 + 2]) = b;
}

__global__ __launch_bounds__(256)
void add_ln_k(const float* __restrict__ X, const float* __restrict__ Y,
              const float* __restrict__ g, const float* __restrict__ b,
              float* __restrict__ out, bf16* __restrict__ oh, bf16* __restrict__ ol)
{
    __shared__ float s1[8], s2[8];
    size_t row = (size_t)blockIdx.x * Dn;
    int tid = threadIdx.x;
    float4 x = *reinterpret_cast<const float4*>(X + row + tid * 4);
    float4 y = *reinterpret_cast<const float4*>(Y + row + tid * 4);
    float4 v; v.x = x.x + y.x; v.y = x.y + y.y; v.z = x.z + y.z; v.w = x.w + y.w;
    float sum = v.x + v.y + v.z + v.w;
    float sq  = v.x*v.x + v.y*v.y + v.z*v.z + v.w*v.w;
#pragma unroll
    for (int o = 16; o; o >>= 1) {
        sum += __shfl_xor_sync(0xffffffffu, sum, o);
        sq  += __shfl_xor_sync(0xffffffffu, sq,  o);
    }
    if ((tid & 31) == 0) { s1[tid >> 5] = sum; s2[tid >> 5] = sq; }
    __syncthreads();
    if (tid == 0) {
        float a = 0.f, c = 0.f;
#pragma unroll
        for (int i = 0; i < 8; i++) { a += s1[i]; c += s2[i]; }
        s1[0] = a; s2[0] = c;
    }
    __syncthreads();
    float mean = s1[0] * (1.f / Dn);
    float var  = s2[0] * (1.f / Dn) - mean * mean;
    float inv  = rsqrtf(var + 1e-5f);
    float4 gg = *reinterpret_cast<const float4*>(g + tid * 4);
    float4 bb = *reinterpret_cast<const float4*>(b + tid * 4);
    float4 o;
    o.x = (v.x - mean) * inv * gg.x + bb.x;
    o.y = (v.y - mean) * inv * gg.y + bb.y;
    o.z = (v.z - mean) * inv * gg.z + bb.z;
    o.w = (v.w - mean) * inv * gg.w + bb.w;
    if (out) *reinterpret_cast<float4*>(out + row + tid * 4) = o;
    if (oh) {
        bf16 h0, l0, h1, l1, h2, l2, h3, l3;
        split2(o.x, h0, l0); split2(o.y, h1, l1);
        split2(o.z, h2, l2); split2(o.w, h3, l3);
        bf162 a2, b2;
        size_t o0 = row + tid * 4;
        a2.x = h0; a2.y = h1; b2.x = h2; b2.y = h3;
        *reinterpret_cast<bf162*>(&oh[o0]) = a2;
        *reinterpret_cast<bf162*>(&oh[o0 + 2]) = b2;
        a2.x = l0; a2.y = l1; b2.x = l2; b2.y = l3;
        *reinterpret_cast<bf162*>(&ol[o0]) = a2;
        *reinterpret_cast<bf162*>(&ol[o0 + 2]) = b2;
    }
}

// ---------------- host side ----------------
extern "C" void kernel_launch(void* const* d_in, const int* in_sizes, int n_in,
                              void* d_out, int out_size)
{
    const float* src = (const float*)d_in[0];
    const float* aux = (const float*)d_in[1];
    const float* Wu  = (const float*)d_in[2];
    const float* bu  = (const float*)d_in[3];
    const float* Wv  = (const float*)d_in[4];
    const float* bv  = (const float*)d_in[5];
    const float* Wo  = (const float*)d_in[6];
    const float* bo  = (const float*)d_in[7];
    const float* W1  = (const float*)d_in[8];
    const float* b1  = (const float*)d_in[9];
    const float* W2  = (const float*)d_in[10];
    const float* b2  = (const float*)d_in[11];
    const float* g1  = (const float*)d_in[12];
    const float* be1 = (const float*)d_in[13];
    const float* g2  = (const float*)d_in[14];
    const float* be2 = (const float*)d_in[15];
    const int* src_mask = (const int*)d_in[16];
    const int* aux_mask = (const int*)d_in[17];
    float* out = (float*)d_out;

    unsigned char* pool;
    cudaGetSymbolAddress((void**)&pool, g_pool);
    float* comb = (float*)(pool + O_COMB);
    float* proj = (float*)(pool + O_PROJ);
    float* o1   = (float*)(pool + O_O1);
    bf16 *srch = (bf16*)(pool + O_SRCH), *srcl = (bf16*)(pool + O_SRCL);
    bf16 *auxh = (bf16*)(pool + O_AUXH), *auxl = (bf16*)(pool + O_AUXL);
    bf16 *WuTh = (bf16*)(pool + O_WUTH), *WuTl = (bf16*)(pool + O_WUTL);
    bf16 *WvTh = (bf16*)(pool + O_WVTH), *WvTl = (bf16*)(pool + O_WVTL);
    bf16 *WoTh = (bf16*)(pool + O_WOTH), *WoTl = (bf16*)(pool + O_WOTL);
    bf16 *W1Th = (bf16*)(pool + O_W1TH), *W1Tl = (bf16*)(pool + O_W1TL);
    bf16 *W2Th = (bf16*)(pool + O_W2TH), *W2Tl = (bf16*)(pool + O_W2TL);
    bf16 *quh = (bf16*)(pool + O_QUH), *qul = (bf16*)(pool + O_QUL);
    bf16 *qvh = (bf16*)(pool + O_QVH), *qvl = (bf16*)(pool + O_QVL);
    bf16 *s1h = (bf16*)(pool + O_S1H), *s1l = (bf16*)(pool + O_S1L);
    bf16 *s2h = (bf16*)(pool + O_S2H), *s2l = (bf16*)(pool + O_S2L);
    bf16 *s1tph = (bf16*)(pool + O_S1TPH), *s1tpl = (bf16*)(pool + O_S1TPL);
    bf16 *s2tph = (bf16*)(pool + O_S2TPH), *s2tpl = (bf16*)(pool + O_S2TPL);
    bf16 *s1ph = (bf16*)(pool + O_S1PH), *s1pl = (bf16*)(pool + O_S1PL);
    bf16 *s2ph = (bf16*)(pool + O_S2PH), *s2pl = (bf16*)(pool + O_S2PL);
    bf16 *atth = (bf16*)(pool + O_ATTH), *attl = (bf16*)(pool + O_ATTL);
    bf16 *vtuh = (bf16*)(pool + O_VTUH), *vtul = (bf16*)(pool + O_VTUL);
    bf16 *vtvh = (bf16*)(pool + O_VTVH), *vtvl = (bf16*)(pool + O_VTVL);
    bf16 *hdh = (bf16*)(pool + O_HDH), *hdl = (bf16*)(pool + O_HDL);
    bf16 *o1h = (bf16*)(pool + O_O1H), *o1l = (bf16*)(pool + O_O1L);
    bf16 *ffhh = (bf16*)(pool + O_FFHH), *ffhl = (bf16*)(pool + O_FFHL);
    int *idxU = (int*)(pool + O_IDXU), *idxV = (int*)(pool + O_IDXV);
    int *kiU = (int*)(pool + O_KIU), *kiV = (int*)(pool + O_KIV);

    cudaFuncSetAttribute(hgemm_k<128>, cudaFuncAttributeMaxDynamicSharedMemorySize, 2 * (2 * 16384 + 2 * 128 * 128) + 1024);
    cudaFuncSetAttribute(hgemm_k<64>,  cudaFuncAttributeMaxDynamicSharedMemorySize, 2 * (2 * 16384 + 2 * 64 * 128) + 1024);
    cudaFuncSetAttribute(comb_mma_k,   cudaFuncAttributeMaxDynamicSharedMemorySize, SMEM_COMB);

    const int SM128 = 2 * (2 * 16384 + 2 * 128 * 128) + 1024;
    const int SM64  = 2 * (2 * 16384 + 2 * 64 * 128) + 1024;

    const long long sQKVr = (long long)Tn * 3 * An;
    const long long sT2   = (long long)Tn * Tn;
    const long long sHT2  = (long long)Hn * Tn * Tn;

    // ---- mask index scans
    maskidx_k<<<2, 1024>>>(aux_mask, idxU, kiU);
    maskidx_k<<<2, 1024>>>(src_mask, idxV, kiV);

    // ---- input & weight splits
    split_k<<<(int)((N_BTD / 4 + 255) / 256), 256>>>((const float4*)src, (bf162*)srch, (bf162*)srcl, (int)(N_BTD / 4));
    split_k<<<(int)((N_BTD / 4 + 255) / 256), 256>>>((const float4*)aux, (bf162*)auxh, (bf162*)auxl, (int)(N_BTD / 4));
    wsplitT_k<<<dim3(3 * An / 32, Dn / 32), 256>>>(Wu, WuTh, WuTl, 3 * An, Dn);
    wsplitT_k<<<dim3(3 * An / 32, Dn / 32), 256>>>(Wv, WvTh, WvTl, 3 * An, Dn);
    wsplitT_k<<<dim3(Dn / 32, An / 32), 256>>>(Wo, WoTh, WoTl, Dn, An);
    wsplitT_k<<<dim3(Fn / 32, Dn / 32), 256>>>(W1, W1Th, W1Tl, Fn, Dn);
    wsplitT_k<<<dim3(Dn / 32, Fn / 32), 256>>>(W2, W2Th, W2Tl, Dn, Fn);

    // ---- QKV projections
    hgemm_k<128><<<dim3(24, 16, 1), 256, SM128>>>(
        srch, srcl, WuTh, WuTl, nullptr, quh, qul,
        Dn, Dn, Dn, 3 * An, 0, 0, 0, 0, 0, 0, 1, bu, nullptr, 0, 1.f, 0);
    hgemm_k<128><<<dim3(24, 16, 1), 256, SM128>>>(
        auxh, auxl, WvTh, WvTl, nullptr, qvh, qvl,
        Dn, Dn, Dn, 3 * An, 0, 0, 0, 0, 0, 0, 1, bv, nullptr, 0, 1.f, 0);

    // ---- sim1 / sim2 (masked, scaled)
    hgemm_k<128><<<dim3(8, 8, ZHn), 256, SM128>>>(
        quh, qul, qvh + An, qvl + An, nullptr, s1h, s1l,
        HDn, 3 * An, 3 * An, Tn,
        sQKVr, HDn, sQKVr, HDn, sHT2, sT2, Hn, nullptr, aux_mask, Tn, 0.125f, 0);
    hgemm_k<128><<<dim3(8, 8, ZHn), 256, SM128>>>(
        qvh, qvl, quh + An, qul + An, nullptr, s2h, s2l,
        HDn, 3 * An, 3 * An, Tn,
        sQKVr, HDn, sQKVr, HDn, sHT2, sT2, Hn, nullptr, src_mask, Tn, 0.125f, 0);

    // ---- masked-K packing for comb operands
    packg_k<<<dim3(4, 1024, ZHn), 256>>>(s1h, s1l, s1ph, s1pl, idxU, kiU);   // A for comb U
    packt_k<<<dim3(32, 32, ZHn), 256>>>(s2h, s2l, s2tph, s2tpl, idxU, kiU);  // B for comb U
    packg_k<<<dim3(4, 1024, ZHn), 256>>>(s2h, s2l, s2ph, s2pl, idxV, kiV);   // A for comb V
    packt_k<<<dim3(32, 32, ZHn), 256>>>(s1h, s1l, s1tph, s1tpl, idxV, kiV);  // B for comb V

    // ---- V^T splits
    btran_k<<<dim3(2, 32, ZHn), 256>>>(quh + 2 * An, qul + 2 * An, vtuh, vtul,
                                       3 * An, Tn, sQKVr, HDn, (long long)HDn * Tn, Hn);
    btran_k<<<dim3(2, 32, ZHn), 256>>>(qvh + 2 * An, qvl + 2 * An, vtvh, vtvl,
                                       3 * An, Tn, sQKVr, HDn, (long long)HDn * Tn, Hn);

    dim3 cgrid(8, 8, ZHn);

    // ================= stream U =================
    comb_mma_k<<<cgrid, 256, SMEM_COMB>>>(s1ph, s1pl, s2tph, s2tpl, comb, kiU);
    softmax_bf_k<<<ZHn * Tn, 256>>>(comb, atth, attl);
    hgemm_k<64><<<dim3(1, 8, ZHn), 256, SM64>>>(
        atth, attl, vtuh, vtul, nullptr, hdh, hdl,
        Tn, Tn, Tn, An,
        (long long)Hn * sT2, sT2, (long long)Hn * HDn * Tn, (long long)HDn * Tn,
        (long long)Tn * An, HDn, Hn, nullptr, nullptr, 0, 1.f, 0);
    hgemm_k<128><<<dim3(8, 16, 1), 256, SM128>>>(
        hdh, hdl, WoTh, WoTl, proj, nullptr, nullptr,
        An, An, An, Dn, 0, 0, 0, 0, 0, 0, 1, bo, nullptr, 0, 1.f, 0);
    add_ln_k<<<BTn, 256>>>(src, proj, g1, be1, o1, o1h, o1l);
    hgemm_k<128><<<dim3(32, 16, 1), 256, SM128>>>(
        o1h, o1l, W1Th, W1Tl, nullptr, ffhh, ffhl,
        Dn, Dn, Dn, Fn, 0, 0, 0, 0, 0, 0, 1, b1, nullptr, 0, 1.f, 1);
    hgemm_k<128><<<dim3(8, 16, 1), 256, SM128>>>(
        ffhh, ffhl, W2Th, W2Tl, proj, nullptr, nullptr,
        Fn, Fn, Fn, Dn, 0, 0, 0, 0, 0, 0, 1, b2, nullptr, 0, 1.f, 0);
    add_ln_k<<<BTn, 256>>>(o1, proj, g2, be2, out, nullptr, nullptr);

    // ================= stream V =================
    comb_mma_k<<<cgrid, 256, SMEM_COMB>>>(s2ph, s2pl, s1tph, s1tpl, comb, kiV);
    softmax_bf_k<<<ZHn * Tn, 256>>>(comb, atth, attl);
    hgemm_k<64><<<dim3(1, 8, ZHn), 256, SM64>>>(
        atth, attl, vtvh, vtvl, nullptr, hdh, hdl,
        Tn, Tn, Tn, An,
        (long long)Hn * sT2, sT2, (long long)Hn * HDn * Tn, (long long)HDn * Tn,
        (long long)Tn * An, HDn, Hn, nullptr, nullptr, 0, 1.f, 0);
    hgemm_k<128><<<dim3(8, 16, 1), 256, SM128>>>(
        hdh, hdl, WoTh, WoTl, proj, nullptr, nullptr,
        An, An, An, Dn, 0, 0, 0, 0, 0, 0, 1, bo, nullptr, 0, 1.f, 0);
    add_ln_k<<<BTn, 256>>>(aux, proj, g1, be1, o1, o1h, o1l);
    hgemm_k<128><<<dim3(32, 16, 1), 256, SM128>>>(
        o1h, o1l, W1Th, W1Tl, nullptr, ffhh, ffhl,
        Dn, Dn, Dn, Fn, 0, 0, 0, 0, 0, 0, 1, b1, nullptr, 0, 1.f, 1);
    hgemm_k<128><<<dim3(8, 16, 1), 256, SM128>>>(
        ffhh, ffhl, W2Th, W2Tl, proj, nullptr, nullptr,
        Fn, Fn, Fn, Dn, 0, 0, 0, 0, 0, 0, 1, b2, nullptr, 0, 1.f, 0);
    add_ln_k<<<BTn, 256>>>(o1, proj, g2, be2, out + (size_t)BTn * Dn, nullptr, nullptr);
}